// round 8
// baseline (speedup 1.0000x reference)
#include <cuda_runtime.h>
#include <cuda_fp16.h>
#include <cstdint>
#include <cstddef>

// Problem constants
#define Bsz 4
#define Lsz 512
#define Dsz 768
#define Wsz 12
#define Ksz (Lsz * Wsz)
#define NTOK (Bsz * Ksz)     // 24576
#define BLROWS (Bsz * Lsz)   // 2048
#define FFD 3072
#define CATD 1536

// fp16 weight buffer offsets (elements)
#define OFF_W1A 0u
#define OFF_W1B 2359296u
#define OFF_W2A 4718592u
#define OFF_W2B 7077888u
#define OFF_W3  9437184u
#define OFF_W4  14155776u
#define WTOT    16515072u

// Static device scratch (allocation-free rule)
__device__ alignas(128) __half g_wh[WTOT];
__device__ alignas(128) __half g_h_hi[(size_t)BLROWS * Dsz];
__device__ alignas(128) __half g_h_lo[(size_t)BLROWS * Dsz];
__device__ alignas(128) __half g_hid_hi[(size_t)NTOK * FFD];
__device__ alignas(128) __half g_hid_lo[(size_t)NTOK * FFD];
__device__ alignas(128) __half g_cat_hi[(size_t)NTOK * CATD];
__device__ alignas(128) __half g_cat_lo[(size_t)NTOK * CATD];
__device__ alignas(128) float  g_se[(size_t)BLROWS * CATD];
__device__ int g_is64;

// ---------------------------------------------------------------------------
// span_idx dtype detection (int64 vs int32)
// ---------------------------------------------------------------------------
__global__ void detect_idx_kernel(const unsigned int* __restrict__ sp, int nhalf) {
    __shared__ int s_any;
    if (threadIdx.x == 0) s_any = 0;
    __syncthreads();
    int found = 0;
    for (int i = threadIdx.x; i < nhalf; i += blockDim.x)
        if (sp[2 * i + 1] != 0u) found = 1;
    if (found) atomicOr(&s_any, 1);
    __syncthreads();
    if (threadIdx.x == 0) g_is64 = (s_any == 0) ? 1 : 0;
}

// ---------------------------------------------------------------------------
// fp32 -> exact fp16 (hi, lo) split (A operands)
// ---------------------------------------------------------------------------
__global__ void splitA_kernel(const float* __restrict__ x,
                              __half* __restrict__ hi,
                              __half* __restrict__ lo, int n4)
{
    int t = blockIdx.x * blockDim.x + threadIdx.x;
    if (t >= n4) return;
    float4 v = ((const float4*)x)[t];
    __half h0 = __float2half_rn(v.x), h1 = __float2half_rn(v.y);
    __half h2 = __float2half_rn(v.z), h3 = __float2half_rn(v.w);
    __half l0 = __float2half_rn(v.x - __half2float(h0));
    __half l1 = __float2half_rn(v.y - __half2float(h1));
    __half l2 = __float2half_rn(v.z - __half2float(h2));
    __half l3 = __float2half_rn(v.w - __half2float(h3));
    __half hh[4] = {h0, h1, h2, h3};
    __half ll[4] = {l0, l1, l2, l3};
    ((uint2*)hi)[t] = *(uint2*)hh;
    ((uint2*)lo)[t] = *(uint2*)ll;
}

// fp32 -> fp16 single rounding (B / weight operands)
__global__ void convB_kernel(const float* __restrict__ x,
                             __half* __restrict__ h, int n4)
{
    int t = blockIdx.x * blockDim.x + threadIdx.x;
    if (t >= n4) return;
    float4 v = ((const float4*)x)[t];
    __half hh[4] = {__float2half_rn(v.x), __float2half_rn(v.y),
                    __float2half_rn(v.z), __float2half_rn(v.w)};
    ((uint2*)h)[t] = *(uint2*)hh;
}

// ---------------------------------------------------------------------------
// PTX helpers
// ---------------------------------------------------------------------------
__device__ __forceinline__ uint32_t smem_u32(const void* p) {
    return (uint32_t)__cvta_generic_to_shared(p);
}
__device__ __forceinline__ void ldm_x4(uint32_t* r, uint32_t addr) {
    asm volatile("ldmatrix.sync.aligned.m8n8.x4.shared.b16 {%0,%1,%2,%3}, [%4];"
                 : "=r"(r[0]), "=r"(r[1]), "=r"(r[2]), "=r"(r[3]) : "r"(addr));
}
__device__ __forceinline__ void mma_f16(float* d, const uint32_t* a, const uint32_t* b) {
    asm volatile(
        "mma.sync.aligned.m16n8k16.row.col.f32.f16.f16.f32 "
        "{%0,%1,%2,%3},{%4,%5,%6,%7},{%8,%9},{%0,%1,%2,%3};"
        : "+f"(d[0]), "+f"(d[1]), "+f"(d[2]), "+f"(d[3])
        : "r"(a[0]), "r"(a[1]), "r"(a[2]), "r"(a[3]), "r"(b[0]), "r"(b[1]));
}
__device__ __forceinline__ void cp16(uint32_t dst, const void* src) {
    asm volatile("cp.async.cg.shared.global [%0], [%1], 16;" :: "r"(dst), "l"(src));
}

// ---------------------------------------------------------------------------
// 2-pass split-fp16 tensor GEMM (NT): C = (Ah+Al)*Bh^T + bias, opt ReLU.
// Block 128xBNx32 (BN=256 or 128), 3-stage cp.async, 8 warps (2x4),
// warp tile 64x(BN/4). gridDim.z batching via zAoff/zBoff/zCoff elements;
// zBias: bias = (z ? bias2 : bias1). Else column split at nsplit.
// mode 0: fp32 C. mode 1: relu + exact fp16 hi/lo split C.
// Requires M%128==0, N%BN==0, K%32==0.
// ---------------------------------------------------------------------------
template<int BN>
__global__ __launch_bounds__(256, 1)
void gemm2p_kernel(const __half* __restrict__ Ah,
                   const __half* __restrict__ Al,
                   const __half* __restrict__ Bh,
                   const float* __restrict__ bias1,
                   const float* __restrict__ bias2, int nsplit,
                   float* __restrict__ Cf,
                   __half* __restrict__ Ch,
                   __half* __restrict__ Cl,
                   int N, int K, int lda, int ldc, int mode,
                   int zAoff, int zBoff, int zCoff, int zBias)
{
    constexpr int WN    = BN / 4;      // warp N tile: 64 or 32
    constexpr int NF    = WN / 8;      // n-fragments: 8 or 4
    constexpr int NP    = WN / 16;     // B ldm_x4 loads: 4 or 2
    constexpr int TILEA = 128 * 80;    // 10240 bytes (64B data + 16B pad rows)
    constexpr int TILEB = BN * 80;
    constexpr int STAGE = 2 * TILEA + TILEB;

    extern __shared__ char smem[];
    const uint32_t sbase = smem_u32(smem);

    const int tid  = threadIdx.x;
    const int lane = tid & 31;
    const int wid  = tid >> 5;
    const int wm   = (wid >> 2) * 64;
    const int wn   = (wid & 3) * WN;
    const int bm   = blockIdx.y << 7;
    const int bn   = blockIdx.x * BN;
    const int z    = blockIdx.z;

    const __half* aSrcH = Ah + (size_t)z * zAoff + (size_t)bm * lda;
    const __half* aSrcL = Al + (size_t)z * zAoff + (size_t)bm * lda;
    const __half* bSrc  = Bh + (size_t)z * zBoff + (size_t)bn * K;

    float acc[4][NF][4];
#pragma unroll
    for (int i = 0; i < 4; i++)
#pragma unroll
        for (int j = 0; j < NF; j++)
#pragma unroll
            for (int r = 0; r < 4; r++) acc[i][j][r] = 0.f;

    const int nk = K >> 5;

    auto issue = [&](int kt) {
        const uint32_t st = sbase + (kt % 3) * STAGE;
        const int kb = kt << 5;
#pragma unroll
        for (int i = 0; i < 2; i++) {                // A: 512 chunks (hi) + 512 (lo)
            const int c   = tid + 256 * i;
            const int row = c >> 2;
            const int ch  = c & 3;
            const uint32_t doff = (uint32_t)row * 80 + ch * 16;
            cp16(st + doff,         aSrcH + (size_t)row * lda + kb + ch * 8);
            cp16(st + TILEA + doff, aSrcL + (size_t)row * lda + kb + ch * 8);
        }
#pragma unroll
        for (int i = 0; i < BN / 64; i++) {          // B: BN*4 chunks
            const int c   = tid + 256 * i;
            const int row = c >> 2;
            const int ch  = c & 3;
            const uint32_t doff = (uint32_t)row * 80 + ch * 16;
            cp16(st + 2 * TILEA + doff, bSrc + (size_t)row * K + kb + ch * 8);
        }
    };

    // ldmatrix lane mapping
    const int aq    = lane >> 3;
    const int arow  = ((aq & 1) << 3) + (lane & 7);
    const int acol  = (aq >> 1) << 3;
    const int brow4 = ((lane >> 4) << 3) + (lane & 7);
    const int bcol4 = ((lane >> 3) & 1) << 3;

    issue(0);
    asm volatile("cp.async.commit_group;" ::: "memory");
    issue(1);
    asm volatile("cp.async.commit_group;" ::: "memory");

    for (int kt = 0; kt < nk; kt++) {
        asm volatile("cp.async.wait_group 1;" ::: "memory");
        __syncthreads();
        if (kt + 2 < nk) issue(kt + 2);
        asm volatile("cp.async.commit_group;" ::: "memory");

        const uint32_t st = sbase + (kt % 3) * STAGE;

#pragma unroll
        for (int kk = 0; kk < 32; kk += 16) {
            uint32_t aH[4][4], aL[4][4], bb[NP][4];
#pragma unroll
            for (int mi = 0; mi < 4; mi++) {
                const uint32_t off = (uint32_t)(wm + mi * 16 + arow) * 80 + (kk + acol) * 2;
                ldm_x4(aH[mi], st + off);
                ldm_x4(aL[mi], st + TILEA + off);
            }
#pragma unroll
            for (int p = 0; p < NP; p++) {
                const uint32_t off = (uint32_t)(wn + p * 16 + brow4) * 80 + (kk + bcol4) * 2;
                ldm_x4(bb[p], st + 2 * TILEA + off);
            }
            // hi pass: 4*NP*2 MMAs back-to-back
#pragma unroll
            for (int mi = 0; mi < 4; mi++)
#pragma unroll
                for (int p = 0; p < NP; p++) {
                    mma_f16(acc[mi][2 * p],     aH[mi], &bb[p][0]);
                    mma_f16(acc[mi][2 * p + 1], aH[mi], &bb[p][2]);
                }
            // lo pass
#pragma unroll
            for (int mi = 0; mi < 4; mi++)
#pragma unroll
                for (int p = 0; p < NP; p++) {
                    mma_f16(acc[mi][2 * p],     aL[mi], &bb[p][0]);
                    mma_f16(acc[mi][2 * p + 1], aL[mi], &bb[p][2]);
                }
        }
    }

    // Epilogue
    float* Cfz = Cf ? Cf + (size_t)z * zCoff : nullptr;
    __half* Chz = Ch ? Ch + (size_t)z * zCoff : nullptr;
    __half* Clz = Cl ? Cl + (size_t)z * zCoff : nullptr;
    const float* bA = (zBias && z) ? bias2 : bias1;

    const int lr = lane >> 2;
    const int lc = (lane & 3) * 2;
#pragma unroll
    for (int mi = 0; mi < 4; mi++) {
#pragma unroll
        for (int ni = 0; ni < NF; ni++) {
            const int gm = bm + wm + mi * 16 + lr;
            const int gc = bn + wn + ni * 8 + lc;
            const float b0 = (gc < nsplit)     ? bA[gc]     : bias2[gc - nsplit];
            const float b1 = (gc + 1 < nsplit) ? bA[gc + 1] : bias2[gc + 1 - nsplit];
            float v0 = acc[mi][ni][0] + b0;
            float v1 = acc[mi][ni][1] + b1;
            float v2 = acc[mi][ni][2] + b0;
            float v3 = acc[mi][ni][3] + b1;
            if (mode == 0) {
                *(float2*)(Cfz + (size_t)gm * ldc + gc)       = make_float2(v0, v1);
                *(float2*)(Cfz + (size_t)(gm + 8) * ldc + gc) = make_float2(v2, v3);
            } else {
                v0 = fmaxf(v0, 0.f); v1 = fmaxf(v1, 0.f);
                v2 = fmaxf(v2, 0.f); v3 = fmaxf(v3, 0.f);
                __half h0 = __float2half_rn(v0), h1 = __float2half_rn(v1);
                __half h2 = __float2half_rn(v2), h3 = __float2half_rn(v3);
                __half l0 = __float2half_rn(v0 - __half2float(h0));
                __half l1 = __float2half_rn(v1 - __half2float(h1));
                __half l2 = __float2half_rn(v2 - __half2float(h2));
                __half l3 = __float2half_rn(v3 - __half2float(h3));
                __half p01[2] = {h0, h1}, p23[2] = {h2, h3};
                __half q01[2] = {l0, l1}, q23[2] = {l2, l3};
                *(uint32_t*)(Chz + (size_t)gm * ldc + gc)       = *(uint32_t*)p01;
                *(uint32_t*)(Clz + (size_t)gm * ldc + gc)       = *(uint32_t*)q01;
                *(uint32_t*)(Chz + (size_t)(gm + 8) * ldc + gc) = *(uint32_t*)p23;
                *(uint32_t*)(Clz + (size_t)(gm + 8) * ldc + gc) = *(uint32_t*)q23;
            }
        }
    }
}

// ---------------------------------------------------------------------------
// Gather spans from combined se[2048,1536], ReLU, exact fp16 split
// ---------------------------------------------------------------------------
__global__ void gather_cat_kernel(const float* __restrict__ se,
                                  const void* __restrict__ span,
                                  __half* __restrict__ cat_hi,
                                  __half* __restrict__ cat_lo)
{
    const int QD = CATD / 4;
    int t = blockIdx.x * blockDim.x + threadIdx.x;
    if (t >= NTOK * QD) return;
    int r = t / QD;
    int q = t - r * QD;
    int b = r / Ksz;
    int col = q * 4;

    int which = (col < Dsz) ? 0 : 1;
    size_t pos = (size_t)r * 2 + which;
    long long idx;
    if (g_is64) idx = ((const long long*)span)[pos];
    else        idx = (long long)((const int*)span)[pos];

    const float* src = se + ((size_t)b * Lsz + idx) * CATD + col;

    float4 v = *(const float4*)src;
    v.x = fmaxf(v.x, 0.f); v.y = fmaxf(v.y, 0.f);
    v.z = fmaxf(v.z, 0.f); v.w = fmaxf(v.w, 0.f);

    __half h0 = __float2half_rn(v.x), h1 = __float2half_rn(v.y);
    __half h2 = __float2half_rn(v.z), h3 = __float2half_rn(v.w);
    __half l0 = __float2half_rn(v.x - __half2float(h0));
    __half l1 = __float2half_rn(v.y - __half2float(h1));
    __half l2 = __float2half_rn(v.z - __half2float(h2));
    __half l3 = __float2half_rn(v.w - __half2float(h3));
    __half hh[4] = {h0, h1, h2, h3};
    __half ll[4] = {l0, l1, l2, l3};
    ((uint2*)cat_hi)[t] = *(uint2*)hh;
    ((uint2*)cat_lo)[t] = *(uint2*)ll;
}

// ---------------------------------------------------------------------------
// Launch
// ---------------------------------------------------------------------------
extern "C" void kernel_launch(void* const* d_in, const int* in_sizes, int n_in,
                              void* d_out, int out_size)
{
    const float* h   = (const float*)d_in[0];
    const void*  sp  = d_in[1];
    const float* ws1 = (const float*)d_in[2];
    const float* bs1 = (const float*)d_in[3];
    const float* ws2 = (const float*)d_in[4];
    const float* bs2 = (const float*)d_in[5];
    const float* we1 = (const float*)d_in[6];
    const float* be1 = (const float*)d_in[7];
    const float* we2 = (const float*)d_in[8];
    const float* be2 = (const float*)d_in[9];
    const float* wo1 = (const float*)d_in[10];
    const float* bo1 = (const float*)d_in[11];
    const float* wo2 = (const float*)d_in[12];
    const float* bo2 = (const float*)d_in[13];
    float* out = (float*)d_out;

    __half *wh, *hhi, *hlo, *dhhi, *dhlo, *chi, *clo;
    float *se;
    cudaGetSymbolAddress((void**)&wh,   g_wh);
    cudaGetSymbolAddress((void**)&hhi,  g_h_hi);
    cudaGetSymbolAddress((void**)&hlo,  g_h_lo);
    cudaGetSymbolAddress((void**)&dhhi, g_hid_hi);
    cudaGetSymbolAddress((void**)&dhlo, g_hid_lo);
    cudaGetSymbolAddress((void**)&chi,  g_cat_hi);
    cudaGetSymbolAddress((void**)&clo,  g_cat_lo);
    cudaGetSymbolAddress((void**)&se,   g_se);

    const int SM256 = 3 * (2 * 128 * 80 + 256 * 80);   // 122880
    const int SM128 = 3 * (2 * 128 * 80 + 128 * 80);   // 92160
    cudaFuncSetAttribute(gemm2p_kernel<256>,
                         cudaFuncAttributeMaxDynamicSharedMemorySize, SM256);
    cudaFuncSetAttribute(gemm2p_kernel<128>,
                         cudaFuncAttributeMaxDynamicSharedMemorySize, SM128);

    detect_idx_kernel<<<1, 256>>>((const unsigned int*)sp, NTOK);

    // Precision prep
    {
        int n4 = (BLROWS * Dsz) / 4;
        splitA_kernel<<<(n4 + 255) / 256, 256>>>(h, hhi, hlo, n4);
        n4 = (FFD * Dsz) / 4;
        convB_kernel<<<(n4 + 255) / 256, 256>>>(ws1, wh + OFF_W1A, n4);
        convB_kernel<<<(n4 + 255) / 256, 256>>>(we1, wh + OFF_W1B, n4);
        n4 = (Dsz * FFD) / 4;
        convB_kernel<<<(n4 + 255) / 256, 256>>>(ws2, wh + OFF_W2A, n4);
        convB_kernel<<<(n4 + 255) / 256, 256>>>(we2, wh + OFF_W2B, n4);
        n4 = (FFD * CATD) / 4;
        convB_kernel<<<(n4 + 255) / 256, 256>>>(wo1, wh + OFF_W3, n4);
        n4 = (Dsz * FFD) / 4;
        convB_kernel<<<(n4 + 255) / 256, 256>>>(wo2, wh + OFF_W4, n4);
    }

    // L1 fused start|end layer1: hid[2048,6144] = h @ [ws1;we1]^T, relu, split
    gemm2p_kernel<256><<<dim3(6144/256, BLROWS/128, 1), 256, SM256>>>(
        hhi, hlo, wh + OFF_W1A, bs1, be1, FFD, nullptr, dhhi, dhlo,
        6144, Dsz, Dsz, 6144, 1, 0, 0, 0, 0);

    // L2 batched (z=0: start, z=1: end): se[:, z*768 : z*768+768]
    gemm2p_kernel<128><<<dim3(Dsz/128, BLROWS/128, 2), 256, SM128>>>(
        dhhi, dhlo, wh + OFF_W2A, bs2, be2, Dsz, se, nullptr, nullptr,
        Dsz, FFD, 6144, CATD, 0, FFD, (int)(OFF_W2B - OFF_W2A), Dsz, 1);

    // gather + concat + relu + split
    int gthreads = NTOK * (CATD / 4);
    gather_cat_kernel<<<(gthreads + 255) / 256, 256>>>(se, sp, chi, clo);

    // L3: hid[24576,3072] = cat @ wo1^T, relu, split
    gemm2p_kernel<256><<<dim3(FFD/256, NTOK/128, 1), 256, SM256>>>(
        chi, clo, wh + OFF_W3, bo1, bo1, FFD, nullptr, dhhi, dhlo,
        FFD, CATD, CATD, FFD, 1, 0, 0, 0, 0);

    // L4: out[24576,768] = hid @ wo2^T (fp32)
    gemm2p_kernel<256><<<dim3(Dsz/256, NTOK/128, 1), 256, SM256>>>(
        dhhi, dhlo, wh + OFF_W4, bo2, bo2, Dsz, out, nullptr, nullptr,
        Dsz, FFD, FFD, Dsz, 0, 0, 0, 0, 0);
}

// round 9
// speedup vs baseline: 1.0070x; 1.0070x over previous
#include <cuda_runtime.h>
#include <cuda_fp16.h>
#include <cstdint>
#include <cstddef>

// Problem constants
#define Bsz 4
#define Lsz 512
#define Dsz 768
#define Wsz 12
#define Ksz (Lsz * Wsz)
#define NTOK (Bsz * Ksz)     // 24576
#define BLROWS (Bsz * Lsz)   // 2048
#define FFD 3072
#define CATD 1536

// fp16 weight buffer offsets (elements)
#define OFF_W1A 0u
#define OFF_W1B 2359296u
#define OFF_W2A 4718592u
#define OFF_W2B 7077888u
#define OFF_W3  9437184u
#define OFF_W4  14155776u
#define WTOT    16515072u

// Static device scratch (allocation-free rule)
__device__ alignas(128) __half g_wh[WTOT];
__device__ alignas(128) __half g_h_hi[(size_t)BLROWS * Dsz];
__device__ alignas(128) __half g_h_lo[(size_t)BLROWS * Dsz];
__device__ alignas(128) __half g_hid_hi[(size_t)NTOK * FFD];
__device__ alignas(128) __half g_hid_lo[(size_t)NTOK * FFD];
__device__ alignas(128) __half g_cat_hi[(size_t)NTOK * CATD];
__device__ alignas(128) __half g_cat_lo[(size_t)NTOK * CATD];
__device__ alignas(128) float  g_se[(size_t)BLROWS * CATD];
__device__ int g_is64;

// ---------------------------------------------------------------------------
// span_idx dtype detection (int64 vs int32)
// ---------------------------------------------------------------------------
__global__ void detect_idx_kernel(const unsigned int* __restrict__ sp, int nhalf) {
    __shared__ int s_any;
    if (threadIdx.x == 0) s_any = 0;
    __syncthreads();
    int found = 0;
    for (int i = threadIdx.x; i < nhalf; i += blockDim.x)
        if (sp[2 * i + 1] != 0u) found = 1;
    if (found) atomicOr(&s_any, 1);
    __syncthreads();
    if (threadIdx.x == 0) g_is64 = (s_any == 0) ? 1 : 0;
}

// ---------------------------------------------------------------------------
// fp32 -> exact fp16 (hi, lo) split (A operands)
// ---------------------------------------------------------------------------
__global__ void splitA_kernel(const float* __restrict__ x,
                              __half* __restrict__ hi,
                              __half* __restrict__ lo, int n4)
{
    int t = blockIdx.x * blockDim.x + threadIdx.x;
    if (t >= n4) return;
    float4 v = ((const float4*)x)[t];
    __half h0 = __float2half_rn(v.x), h1 = __float2half_rn(v.y);
    __half h2 = __float2half_rn(v.z), h3 = __float2half_rn(v.w);
    __half l0 = __float2half_rn(v.x - __half2float(h0));
    __half l1 = __float2half_rn(v.y - __half2float(h1));
    __half l2 = __float2half_rn(v.z - __half2float(h2));
    __half l3 = __float2half_rn(v.w - __half2float(h3));
    __half hh[4] = {h0, h1, h2, h3};
    __half ll[4] = {l0, l1, l2, l3};
    ((uint2*)hi)[t] = *(uint2*)hh;
    ((uint2*)lo)[t] = *(uint2*)ll;
}

// fp32 -> fp16 single rounding (B / weight operands)
__global__ void convB_kernel(const float* __restrict__ x,
                             __half* __restrict__ h, int n4)
{
    int t = blockIdx.x * blockDim.x + threadIdx.x;
    if (t >= n4) return;
    float4 v = ((const float4*)x)[t];
    __half hh[4] = {__float2half_rn(v.x), __float2half_rn(v.y),
                    __float2half_rn(v.z), __float2half_rn(v.w)};
    ((uint2*)h)[t] = *(uint2*)hh;
}

// ---------------------------------------------------------------------------
// PTX helpers
// ---------------------------------------------------------------------------
__device__ __forceinline__ uint32_t smem_u32(const void* p) {
    return (uint32_t)__cvta_generic_to_shared(p);
}
__device__ __forceinline__ void ldm_x4(uint32_t* r, uint32_t addr) {
    asm volatile("ldmatrix.sync.aligned.m8n8.x4.shared.b16 {%0,%1,%2,%3}, [%4];"
                 : "=r"(r[0]), "=r"(r[1]), "=r"(r[2]), "=r"(r[3]) : "r"(addr));
}
__device__ __forceinline__ void mma_f16(float* d, const uint32_t* a, const uint32_t* b) {
    asm volatile(
        "mma.sync.aligned.m16n8k16.row.col.f32.f16.f16.f32 "
        "{%0,%1,%2,%3},{%4,%5,%6,%7},{%8,%9},{%0,%1,%2,%3};"
        : "+f"(d[0]), "+f"(d[1]), "+f"(d[2]), "+f"(d[3])
        : "r"(a[0]), "r"(a[1]), "r"(a[2]), "r"(a[3]), "r"(b[0]), "r"(b[1]));
}
__device__ __forceinline__ void cp16(uint32_t dst, const void* src) {
    asm volatile("cp.async.cg.shared.global [%0], [%1], 16;" :: "r"(dst), "l"(src));
}

// ---------------------------------------------------------------------------
// 2-pass split-fp16 tensor GEMM (NT): C = (Ah+Al)*Bh^T + bias, opt ReLU.
// Block 128x128x32, 3-stage cp.async, 8 warps (2x4), warp tile 64x32,
// 2 CTAs/SM. gridDim.z batching via zAoff/zBoff/zCoff; zBias: per-z bias.
// mode 0: fp32 C. mode 1: relu + exact fp16 hi/lo split C.
// Requires M%128==0, N%128==0, K%32==0.
// ---------------------------------------------------------------------------
#define TILE_B  (128 * 80)             // 10240 bytes per tile (64B data + 16B pad)
#define STAGE_B (3 * TILE_B)           // 30720 (Ah, Al, Bh)
#define SMEM_DYN (3 * STAGE_B)         // 92160; x2 CTAs = 184320 <= 227KB

__global__ __launch_bounds__(256, 2)
void gemm2p_kernel(const __half* __restrict__ Ah,
                   const __half* __restrict__ Al,
                   const __half* __restrict__ Bh,
                   const float* __restrict__ bias1,
                   const float* __restrict__ bias2, int nsplit,
                   float* __restrict__ Cf,
                   __half* __restrict__ Ch,
                   __half* __restrict__ Cl,
                   int N, int K, int lda, int ldc, int mode,
                   int zAoff, int zBoff, int zCoff, int zBias)
{
    extern __shared__ char smem[];
    const uint32_t sbase = smem_u32(smem);

    const int tid  = threadIdx.x;
    const int lane = tid & 31;
    const int wid  = tid >> 5;
    const int wm   = (wid >> 2) * 64;
    const int wn   = (wid & 3) * 32;
    const int bm   = blockIdx.y << 7;
    const int bn   = blockIdx.x << 7;
    const int z    = blockIdx.z;

    const __half* aSrcH = Ah + (size_t)z * zAoff + (size_t)bm * lda;
    const __half* aSrcL = Al + (size_t)z * zAoff + (size_t)bm * lda;
    const __half* bSrc  = Bh + (size_t)z * zBoff + (size_t)bn * K;

    float acc[4][4][4];
#pragma unroll
    for (int i = 0; i < 4; i++)
#pragma unroll
        for (int j = 0; j < 4; j++)
#pragma unroll
            for (int r = 0; r < 4; r++) acc[i][j][r] = 0.f;

    const int nk = K >> 5;

    // cp.async: 3 tiles x 512 chunks(16B) = 1536 chunks, 6 per thread
    auto issue = [&](int kt) {
        const uint32_t st = sbase + (kt % 3) * STAGE_B;
        const int kb = kt << 5;
#pragma
        for (int i = 0; i < 2; i++) {
            const int c   = tid + 256 * i;
            const int row = c >> 2;
            const int ch  = c & 3;
            const uint32_t doff = (uint32_t)row * 80 + ch * 16;
            cp16(st + doff,              aSrcH + (size_t)row * lda + kb + ch * 8);
            cp16(st + TILE_B + doff,     aSrcL + (size_t)row * lda + kb + ch * 8);
            cp16(st + 2 * TILE_B + doff, bSrc  + (size_t)row * K   + kb + ch * 8);
        }
    };

    // ldmatrix lane mapping
    const int aq    = lane >> 3;
    const int arow  = ((aq & 1) << 3) + (lane & 7);
    const int acol  = (aq >> 1) << 3;
    const int brow4 = ((lane >> 4) << 3) + (lane & 7);
    const int bcol4 = ((lane >> 3) & 1) << 3;

    issue(0);
    asm volatile("cp.async.commit_group;" ::: "memory");
    issue(1);
    asm volatile("cp.async.commit_group;" ::: "memory");

    for (int kt = 0; kt < nk; kt++) {
        asm volatile("cp.async.wait_group 1;" ::: "memory");
        __syncthreads();
        if (kt + 2 < nk) issue(kt + 2);
        asm volatile("cp.async.commit_group;" ::: "memory");

        const uint32_t st = sbase + (kt % 3) * STAGE_B;

#pragma unroll
        for (int kk = 0; kk < 32; kk += 16) {
            uint32_t aH[4][4], aL[4][4], bb[2][4];
#pragma unroll
            for (int mi = 0; mi < 4; mi++) {
                const uint32_t off = (uint32_t)(wm + mi * 16 + arow) * 80 + (kk + acol) * 2;
                ldm_x4(aH[mi], st + off);
                ldm_x4(aL[mi], st + TILE_B + off);
            }
#pragma unroll
            for (int p = 0; p < 2; p++) {
                const uint32_t off = (uint32_t)(wn + p * 16 + brow4) * 80 + (kk + bcol4) * 2;
                ldm_x4(bb[p], st + 2 * TILE_B + off);
            }
            // hi pass: 16 MMAs back-to-back
#pragma unroll
            for (int mi = 0; mi < 4; mi++)
#pragma unroll
                for (int p = 0; p < 2; p++) {
                    mma_f16(acc[mi][2 * p],     aH[mi], &bb[p][0]);
                    mma_f16(acc[mi][2 * p + 1], aH[mi], &bb[p][2]);
                }
            // lo pass: 16 MMAs
#pragma unroll
            for (int mi = 0; mi < 4; mi++)
#pragma unroll
                for (int p = 0; p < 2; p++) {
                    mma_f16(acc[mi][2 * p],     aL[mi], &bb[p][0]);
                    mma_f16(acc[mi][2 * p + 1], aL[mi], &bb[p][2]);
                }
        }
    }

    // Epilogue
    float* Cfz = Cf ? Cf + (size_t)z * zCoff : nullptr;
    __half* Chz = Ch ? Ch + (size_t)z * zCoff : nullptr;
    __half* Clz = Cl ? Cl + (size_t)z * zCoff : nullptr;
    const float* bA = (zBias && z) ? bias2 : bias1;

    const int lr = lane >> 2;
    const int lc = (lane & 3) * 2;
#pragma unroll
    for (int mi = 0; mi < 4; mi++) {
#pragma unroll
        for (int ni = 0; ni < 4; ni++) {
            const int gm = bm + wm + mi * 16 + lr;
            const int gc = bn + wn + ni * 8 + lc;
            const float b0 = (gc < nsplit)     ? bA[gc]     : bias2[gc - nsplit];
            const float b1 = (gc + 1 < nsplit) ? bA[gc + 1] : bias2[gc + 1 - nsplit];
            float v0 = acc[mi][ni][0] + b0;
            float v1 = acc[mi][ni][1] + b1;
            float v2 = acc[mi][ni][2] + b0;
            float v3 = acc[mi][ni][3] + b1;
            if (mode == 0) {
                *(float2*)(Cfz + (size_t)gm * ldc + gc)       = make_float2(v0, v1);
                *(float2*)(Cfz + (size_t)(gm + 8) * ldc + gc) = make_float2(v2, v3);
            } else {
                v0 = fmaxf(v0, 0.f); v1 = fmaxf(v1, 0.f);
                v2 = fmaxf(v2, 0.f); v3 = fmaxf(v3, 0.f);
                __half h0 = __float2half_rn(v0), h1 = __float2half_rn(v1);
                __half h2 = __float2half_rn(v2), h3 = __float2half_rn(v3);
                __half l0 = __float2half_rn(v0 - __half2float(h0));
                __half l1 = __float2half_rn(v1 - __half2float(h1));
                __half l2 = __float2half_rn(v2 - __half2float(h2));
                __half l3 = __float2half_rn(v3 - __half2float(h3));
                __half p01[2] = {h0, h1}, p23[2] = {h2, h3};
                __half q01[2] = {l0, l1}, q23[2] = {l2, l3};
                *(uint32_t*)(Chz + (size_t)gm * ldc + gc)       = *(uint32_t*)p01;
                *(uint32_t*)(Clz + (size_t)gm * ldc + gc)       = *(uint32_t*)q01;
                *(uint32_t*)(Chz + (size_t)(gm + 8) * ldc + gc) = *(uint32_t*)p23;
                *(uint32_t*)(Clz + (size_t)(gm + 8) * ldc + gc) = *(uint32_t*)q23;
            }
        }
    }
}

// ---------------------------------------------------------------------------
// Gather spans from combined se[2048,1536], ReLU, exact fp16 split
// ---------------------------------------------------------------------------
__global__ void gather_cat_kernel(const float* __restrict__ se,
                                  const void* __restrict__ span,
                                  __half* __restrict__ cat_hi,
                                  __half* __restrict__ cat_lo)
{
    const int QD = CATD / 4;
    int t = blockIdx.x * blockDim.x + threadIdx.x;
    if (t >= NTOK * QD) return;
    int r = t / QD;
    int q = t - r * QD;
    int b = r / Ksz;
    int col = q * 4;

    int which = (col < Dsz) ? 0 : 1;
    size_t pos = (size_t)r * 2 + which;
    long long idx;
    if (g_is64) idx = ((const long long*)span)[pos];
    else        idx = (long long)((const int*)span)[pos];

    const float* src = se + ((size_t)b * Lsz + idx) * CATD + col;

    float4 v = *(const float4*)src;
    v.x = fmaxf(v.x, 0.f); v.y = fmaxf(v.y, 0.f);
    v.z = fmaxf(v.z, 0.f); v.w = fmaxf(v.w, 0.f);

    __half h0 = __float2half_rn(v.x), h1 = __float2half_rn(v.y);
    __half h2 = __float2half_rn(v.z), h3 = __float2half_rn(v.w);
    __half l0 = __float2half_rn(v.x - __half2float(h0));
    __half l1 = __float2half_rn(v.y - __half2float(h1));
    __half l2 = __float2half_rn(v.z - __half2float(h2));
    __half l3 = __float2half_rn(v.w - __half2float(h3));
    __half hh[4] = {h0, h1, h2, h3};
    __half ll[4] = {l0, l1, l2, l3};
    ((uint2*)cat_hi)[t] = *(uint2*)hh;
    ((uint2*)cat_lo)[t] = *(uint2*)ll;
}

// ---------------------------------------------------------------------------
// Launch
// ---------------------------------------------------------------------------
extern "C" void kernel_launch(void* const* d_in, const int* in_sizes, int n_in,
                              void* d_out, int out_size)
{
    const float* h   = (const float*)d_in[0];
    const void*  sp  = d_in[1];
    const float* ws1 = (const float*)d_in[2];
    const float* bs1 = (const float*)d_in[3];
    const float* ws2 = (const float*)d_in[4];
    const float* bs2 = (const float*)d_in[5];
    const float* we1 = (const float*)d_in[6];
    const float* be1 = (const float*)d_in[7];
    const float* we2 = (const float*)d_in[8];
    const float* be2 = (const float*)d_in[9];
    const float* wo1 = (const float*)d_in[10];
    const float* bo1 = (const float*)d_in[11];
    const float* wo2 = (const float*)d_in[12];
    const float* bo2 = (const float*)d_in[13];
    float* out = (float*)d_out;

    __half *wh, *hhi, *hlo, *dhhi, *dhlo, *chi, *clo;
    float *se;
    cudaGetSymbolAddress((void**)&wh,   g_wh);
    cudaGetSymbolAddress((void**)&hhi,  g_h_hi);
    cudaGetSymbolAddress((void**)&hlo,  g_h_lo);
    cudaGetSymbolAddress((void**)&dhhi, g_hid_hi);
    cudaGetSymbolAddress((void**)&dhlo, g_hid_lo);
    cudaGetSymbolAddress((void**)&chi,  g_cat_hi);
    cudaGetSymbolAddress((void**)&clo,  g_cat_lo);
    cudaGetSymbolAddress((void**)&se,   g_se);

    cudaFuncSetAttribute(gemm2p_kernel,
                         cudaFuncAttributeMaxDynamicSharedMemorySize, SMEM_DYN);

    detect_idx_kernel<<<1, 256>>>((const unsigned int*)sp, NTOK);

    // Precision prep
    {
        int n4 = (BLROWS * Dsz) / 4;
        splitA_kernel<<<(n4 + 255) / 256, 256>>>(h, hhi, hlo, n4);
        n4 = (FFD * Dsz) / 4;
        convB_kernel<<<(n4 + 255) / 256, 256>>>(ws1, wh + OFF_W1A, n4);
        convB_kernel<<<(n4 + 255) / 256, 256>>>(we1, wh + OFF_W1B, n4);
        n4 = (Dsz * FFD) / 4;
        convB_kernel<<<(n4 + 255) / 256, 256>>>(ws2, wh + OFF_W2A, n4);
        convB_kernel<<<(n4 + 255) / 256, 256>>>(we2, wh + OFF_W2B, n4);
        n4 = (FFD * CATD) / 4;
        convB_kernel<<<(n4 + 255) / 256, 256>>>(wo1, wh + OFF_W3, n4);
        n4 = (Dsz * FFD) / 4;
        convB_kernel<<<(n4 + 255) / 256, 256>>>(wo2, wh + OFF_W4, n4);
    }

    // L1 fused start|end layer1: hid[2048,6144] = h @ [ws1;we1]^T, relu, split
    gemm2p_kernel<<<dim3(6144/128, BLROWS/128, 1), 256, SMEM_DYN>>>(
        hhi, hlo, wh + OFF_W1A, bs1, be1, FFD, nullptr, dhhi, dhlo,
        6144, Dsz, Dsz, 6144, 1, 0, 0, 0, 0);

    // L2 batched (z=0: start, z=1: end): se[:, z*768 : z*768+768]
    gemm2p_kernel<<<dim3(Dsz/128, BLROWS/128, 2), 256, SMEM_DYN>>>(
        dhhi, dhlo, wh + OFF_W2A, bs2, be2, Dsz, se, nullptr, nullptr,
        Dsz, FFD, 6144, CATD, 0, FFD, (int)(OFF_W2B - OFF_W2A), Dsz, 1);

    // gather + concat + relu + split
    int gthreads = NTOK * (CATD / 4);
    gather_cat_kernel<<<(gthreads + 255) / 256, 256>>>(se, sp, chi, clo);

    // L3: hid[24576,3072] = cat @ wo1^T, relu, split
    gemm2p_kernel<<<dim3(FFD/128, NTOK/128, 1), 256, SMEM_DYN>>>(
        chi, clo, wh + OFF_W3, bo1, bo1, FFD, nullptr, dhhi, dhlo,
        FFD, CATD, CATD, FFD, 1, 0, 0, 0, 0);

    // L4: out[24576,768] = hid @ wo2^T (fp32)
    gemm2p_kernel<<<dim3(Dsz/128, NTOK/128, 1), 256, SMEM_DYN>>>(
        dhhi, dhlo, wh + OFF_W4, bo2, bo2, Dsz, out, nullptr, nullptr,
        Dsz, FFD, FFD, Dsz, 0, 0, 0, 0, 0);
}

// round 10
// speedup vs baseline: 1.2439x; 1.2352x over previous
#include <cuda_runtime.h>
#include <cuda_fp16.h>
#include <cstdint>
#include <cstddef>

// Problem constants
#define Bsz 4
#define Lsz 512
#define Dsz 768
#define Wsz 12
#define Ksz (Lsz * Wsz)
#define NTOK (Bsz * Ksz)     // 24576
#define BLROWS (Bsz * Lsz)   // 2048
#define FFD 3072
#define CATD 1536

// fp16 weight buffer offsets (elements)
#define OFF_W1A 0u
#define OFF_W1B 2359296u
#define OFF_W2A 4718592u
#define OFF_W2B 7077888u
#define OFF_W3  9437184u
#define OFF_W4  14155776u
#define WTOT    16515072u

// Static device scratch (allocation-free rule)
__device__ alignas(128) __half g_wh[WTOT];
__device__ alignas(128) __half g_h16[(size_t)BLROWS * Dsz];
__device__ alignas(128) __half g_hid[(size_t)NTOK * FFD];
__device__ alignas(128) __half g_cat[(size_t)NTOK * CATD];
__device__ alignas(128) float  g_se[(size_t)BLROWS * CATD];
__device__ int g_is64;

// ---------------------------------------------------------------------------
// span_idx dtype detection (int64 vs int32)
// ---------------------------------------------------------------------------
__global__ void detect_idx_kernel(const unsigned int* __restrict__ sp, int nhalf) {
    __shared__ int s_any;
    if (threadIdx.x == 0) s_any = 0;
    __syncthreads();
    int found = 0;
    for (int i = threadIdx.x; i < nhalf; i += blockDim.x)
        if (sp[2 * i + 1] != 0u) found = 1;
    if (found) atomicOr(&s_any, 1);
    __syncthreads();
    if (threadIdx.x == 0) g_is64 = (s_any == 0) ? 1 : 0;
}

// ---------------------------------------------------------------------------
// Fused prep: convert h + all 6 weight matrices fp32 -> fp16 in ONE launch.
// Flat quad (float4) index space, segment lookup by cumulative offsets.
// ---------------------------------------------------------------------------
#define QC0 393216u    // h end       (2048*768/4)
#define QC1 983040u    // ws1 end     (+589824)
#define QC2 1572864u   // we1 end
#define QC3 2162688u   // ws2 end
#define QC4 2752512u   // we2 end
#define QC5 3932160u   // wo1 end     (+1179648)
#define QC6 4521984u   // wo2 end
#define PREP_BLOCKS ((QC6 + 255u) / 256u)

__global__ void prep_kernel(const float* __restrict__ h,
                            const float* __restrict__ ws1, const float* __restrict__ we1,
                            const float* __restrict__ ws2, const float* __restrict__ we2,
                            const float* __restrict__ wo1, const float* __restrict__ wo2,
                            __half* __restrict__ h16, __half* __restrict__ wh)
{
    unsigned int t = blockIdx.x * 256u + threadIdx.x;
    if (t >= QC6) return;
    const float* src;
    __half* dst;
    unsigned int off;
    if (t < QC0)      { src = h;   dst = h16;          off = t; }
    else if (t < QC1) { src = ws1; dst = wh + OFF_W1A; off = t - QC0; }
    else if (t < QC2) { src = we1; dst = wh + OFF_W1B; off = t - QC1; }
    else if (t < QC3) { src = ws2; dst = wh + OFF_W2A; off = t - QC2; }
    else if (t < QC4) { src = we2; dst = wh + OFF_W2B; off = t - QC3; }
    else if (t < QC5) { src = wo1; dst = wh + OFF_W3;  off = t - QC4; }
    else              { src = wo2; dst = wh + OFF_W4;  off = t - QC5; }
    float4 v = ((const float4*)src)[off];
    __half hh[4] = {__float2half_rn(v.x), __float2half_rn(v.y),
                    __float2half_rn(v.z), __float2half_rn(v.w)};
    ((uint2*)dst)[off] = *(uint2*)hh;
}

// ---------------------------------------------------------------------------
// PTX helpers
// ---------------------------------------------------------------------------
__device__ __forceinline__ uint32_t smem_u32(const void* p) {
    return (uint32_t)__cvta_generic_to_shared(p);
}
__device__ __forceinline__ void ldm_x4(uint32_t* r, uint32_t addr) {
    asm volatile("ldmatrix.sync.aligned.m8n8.x4.shared.b16 {%0,%1,%2,%3}, [%4];"
                 : "=r"(r[0]), "=r"(r[1]), "=r"(r[2]), "=r"(r[3]) : "r"(addr));
}
__device__ __forceinline__ void mma_f16(float* d, const uint32_t* a, const uint32_t* b) {
    asm volatile(
        "mma.sync.aligned.m16n8k16.row.col.f32.f16.f16.f32 "
        "{%0,%1,%2,%3},{%4,%5,%6,%7},{%8,%9},{%0,%1,%2,%3};"
        : "+f"(d[0]), "+f"(d[1]), "+f"(d[2]), "+f"(d[3])
        : "r"(a[0]), "r"(a[1]), "r"(a[2]), "r"(a[3]), "r"(b[0]), "r"(b[1]));
}
__device__ __forceinline__ void cp16(uint32_t dst, const void* src) {
    asm volatile("cp.async.cg.shared.global [%0], [%1], 16;" :: "r"(dst), "l"(src));
}

// ---------------------------------------------------------------------------
// fp16 tensor GEMM (NT): C = A*B^T + bias, opt ReLU. fp32 accumulate.
// Block 128x128x32, 3-stage cp.async, 8 warps (2x4), warp tile 64x32,
// 2 CTAs/SM. gridDim.z batching via zAoff/zBoff/zCoff; zBias: per-z bias.
// mode 0: fp32 C. mode 1: relu + fp16 C.
// Requires M%128==0, N%128==0, K%32==0.
// ---------------------------------------------------------------------------
#define TILE_B  (128 * 80)             // 10240 bytes per tile (64B data + 16B pad)
#define STAGE_B (2 * TILE_B)           // 20480 (A, B)
#define SMEM_DYN (3 * STAGE_B)         // 61440; x2 CTAs = 122880

__global__ __launch_bounds__(256, 2)
void gemm16_kernel(const __half* __restrict__ A,
                   const __half* __restrict__ B,
                   const float* __restrict__ bias1,
                   const float* __restrict__ bias2, int nsplit,
                   float* __restrict__ Cf,
                   __half* __restrict__ Ch,
                   int N, int K, int lda, int ldc, int mode,
                   int zAoff, int zBoff, int zCoff, int zBias)
{
    extern __shared__ char smem[];
    const uint32_t sbase = smem_u32(smem);

    const int tid  = threadIdx.x;
    const int lane = tid & 31;
    const int wid  = tid >> 5;
    const int wm   = (wid >> 2) * 64;
    const int wn   = (wid & 3) * 32;
    const int bm   = blockIdx.y << 7;
    const int bn   = blockIdx.x << 7;
    const int z    = blockIdx.z;

    const __half* aSrc = A + (size_t)z * zAoff + (size_t)bm * lda;
    const __half* bSrc = B + (size_t)z * zBoff + (size_t)bn * K;

    float acc[4][4][4];
#pragma unroll
    for (int i = 0; i < 4; i++)
#pragma unroll
        for (int j = 0; j < 4; j++)
#pragma unroll
            for (int r = 0; r < 4; r++) acc[i][j][r] = 0.f;

    const int nk = K >> 5;

    // cp.async: 2 tiles x 512 chunks(16B) = 1024 chunks, 4 per thread
    auto issue = [&](int kt) {
        const uint32_t st = sbase + (kt % 3) * STAGE_B;
        const int kb = kt << 5;
#pragma unroll
        for (int i = 0; i < 2; i++) {
            const int c   = tid + 256 * i;
            const int row = c >> 2;
            const int ch  = c & 3;
            const uint32_t doff = (uint32_t)row * 80 + ch * 16;
            cp16(st + doff,          aSrc + (size_t)row * lda + kb + ch * 8);
            cp16(st + TILE_B + doff, bSrc + (size_t)row * K   + kb + ch * 8);
        }
    };

    // ldmatrix lane mapping
    const int aq    = lane >> 3;
    const int arow  = ((aq & 1) << 3) + (lane & 7);
    const int acol  = (aq >> 1) << 3;
    const int brow4 = ((lane >> 4) << 3) + (lane & 7);
    const int bcol4 = ((lane >> 3) & 1) << 3;

    issue(0);
    asm volatile("cp.async.commit_group;" ::: "memory");
    issue(1);
    asm volatile("cp.async.commit_group;" ::: "memory");

    for (int kt = 0; kt < nk; kt++) {
        asm volatile("cp.async.wait_group 1;" ::: "memory");
        __syncthreads();
        if (kt + 2 < nk) issue(kt + 2);
        asm volatile("cp.async.commit_group;" ::: "memory");

        const uint32_t st = sbase + (kt % 3) * STAGE_B;

#pragma unroll
        for (int kk = 0; kk < 32; kk += 16) {
            uint32_t a[4][4], bb[2][4];
#pragma unroll
            for (int mi = 0; mi < 4; mi++) {
                const uint32_t off = (uint32_t)(wm + mi * 16 + arow) * 80 + (kk + acol) * 2;
                ldm_x4(a[mi], st + off);
            }
#pragma unroll
            for (int p = 0; p < 2; p++) {
                const uint32_t off = (uint32_t)(wn + p * 16 + brow4) * 80 + (kk + bcol4) * 2;
                ldm_x4(bb[p], st + TILE_B + off);
            }
            // 16 MMAs back-to-back
#pragma unroll
            for (int mi = 0; mi < 4; mi++)
#pragma unroll
                for (int p = 0; p < 2; p++) {
                    mma_f16(acc[mi][2 * p],     a[mi], &bb[p][0]);
                    mma_f16(acc[mi][2 * p + 1], a[mi], &bb[p][2]);
                }
        }
    }

    // Epilogue
    float* Cfz = Cf ? Cf + (size_t)z * zCoff : nullptr;
    __half* Chz = Ch ? Ch + (size_t)z * zCoff : nullptr;
    const float* bA = (zBias && z) ? bias2 : bias1;

    const int lr = lane >> 2;
    const int lc = (lane & 3) * 2;
#pragma unroll
    for (int mi = 0; mi < 4; mi++) {
#pragma unroll
        for (int ni = 0; ni < 4; ni++) {
            const int gm = bm + wm + mi * 16 + lr;
            const int gc = bn + wn + ni * 8 + lc;
            const float b0 = (gc < nsplit)     ? bA[gc]     : bias2[gc - nsplit];
            const float b1 = (gc + 1 < nsplit) ? bA[gc + 1] : bias2[gc + 1 - nsplit];
            float v0 = acc[mi][ni][0] + b0;
            float v1 = acc[mi][ni][1] + b1;
            float v2 = acc[mi][ni][2] + b0;
            float v3 = acc[mi][ni][3] + b1;
            if (mode == 0) {
                *(float2*)(Cfz + (size_t)gm * ldc + gc)       = make_float2(v0, v1);
                *(float2*)(Cfz + (size_t)(gm + 8) * ldc + gc) = make_float2(v2, v3);
            } else {
                v0 = fmaxf(v0, 0.f); v1 = fmaxf(v1, 0.f);
                v2 = fmaxf(v2, 0.f); v3 = fmaxf(v3, 0.f);
                __half p01[2] = {__float2half_rn(v0), __float2half_rn(v1)};
                __half p23[2] = {__float2half_rn(v2), __float2half_rn(v3)};
                *(uint32_t*)(Chz + (size_t)gm * ldc + gc)       = *(uint32_t*)p01;
                *(uint32_t*)(Chz + (size_t)(gm + 8) * ldc + gc) = *(uint32_t*)p23;
            }
        }
    }
}

// ---------------------------------------------------------------------------
// Gather spans from combined se[2048,1536], ReLU, fp16 -> cat [NTOK, 1536]
// ---------------------------------------------------------------------------
__global__ void gather_cat_kernel(const float* __restrict__ se,
                                  const void* __restrict__ span,
                                  __half* __restrict__ cat)
{
    const int QD = CATD / 4;
    int t = blockIdx.x * blockDim.x + threadIdx.x;
    if (t >= NTOK * QD) return;
    int r = t / QD;
    int q = t - r * QD;
    int b = r / Ksz;
    int col = q * 4;

    int which = (col < Dsz) ? 0 : 1;
    size_t pos = (size_t)r * 2 + which;
    long long idx;
    if (g_is64) idx = ((const long long*)span)[pos];
    else        idx = (long long)((const int*)span)[pos];

    const float* src = se + ((size_t)b * Lsz + idx) * CATD + col;

    float4 v = *(const float4*)src;
    v.x = fmaxf(v.x, 0.f); v.y = fmaxf(v.y, 0.f);
    v.z = fmaxf(v.z, 0.f); v.w = fmaxf(v.w, 0.f);

    __half hh[4] = {__float2half_rn(v.x), __float2half_rn(v.y),
                    __float2half_rn(v.z), __float2half_rn(v.w)};
    ((uint2*)cat)[t] = *(uint2*)hh;
}

// ---------------------------------------------------------------------------
// Launch. Order matters for ncu (-s 5 -c 1): launch #6 is the L3 GEMM.
// ---------------------------------------------------------------------------
extern "C" void kernel_launch(void* const* d_in, const int* in_sizes, int n_in,
                              void* d_out, int out_size)
{
    const float* h   = (const float*)d_in[0];
    const void*  sp  = d_in[1];
    const float* ws1 = (const float*)d_in[2];
    const float* bs1 = (const float*)d_in[3];
    const float* ws2 = (const float*)d_in[4];
    const float* bs2 = (const float*)d_in[5];
    const float* we1 = (const float*)d_in[6];
    const float* be1 = (const float*)d_in[7];
    const float* we2 = (const float*)d_in[8];
    const float* be2 = (const float*)d_in[9];
    const float* wo1 = (const float*)d_in[10];
    const float* bo1 = (const float*)d_in[11];
    const float* wo2 = (const float*)d_in[12];
    const float* bo2 = (const float*)d_in[13];
    float* out = (float*)d_out;

    __half *wh, *h16, *hid, *cat;
    float *se;
    cudaGetSymbolAddress((void**)&wh,  g_wh);
    cudaGetSymbolAddress((void**)&h16, g_h16);
    cudaGetSymbolAddress((void**)&hid, g_hid);
    cudaGetSymbolAddress((void**)&cat, g_cat);
    cudaGetSymbolAddress((void**)&se,  g_se);

    cudaFuncSetAttribute(gemm16_kernel,
                         cudaFuncAttributeMaxDynamicSharedMemorySize, SMEM_DYN);

    // #1
    detect_idx_kernel<<<1, 256>>>((const unsigned int*)sp, NTOK);

    // #2: all fp32->fp16 conversions in one launch
    prep_kernel<<<PREP_BLOCKS, 256>>>(h, ws1, we1, ws2, we2, wo1, wo2, h16, wh);

    // #3: L1 fused start|end layer1: hid[2048,6144] = h @ [ws1;we1]^T, relu
    gemm16_kernel<<<dim3(6144/128, BLROWS/128, 1), 256, SMEM_DYN>>>(
        h16, wh + OFF_W1A, bs1, be1, FFD, nullptr, hid,
        6144, Dsz, Dsz, 6144, 1, 0, 0, 0, 0);

    // #4: L2 batched (z=0: start, z=1: end): se[:, z*768 : z*768+768]
    gemm16_kernel<<<dim3(Dsz/128, BLROWS/128, 2), 256, SMEM_DYN>>>(
        hid, wh + OFF_W2A, bs2, be2, Dsz, se, nullptr,
        Dsz, FFD, 6144, CATD, 0, FFD, (int)(OFF_W2B - OFF_W2A), Dsz, 1);

    // #5: gather + concat + relu -> fp16 cat
    int gthreads = NTOK * (CATD / 4);
    gather_cat_kernel<<<(gthreads + 255) / 256, 256>>>(se, sp, cat);

    // #6: L3 (dominant, profiled): hid[24576,3072] = cat @ wo1^T, relu
    gemm16_kernel<<<dim3(FFD/128, NTOK/128, 1), 256, SMEM_DYN>>>(
        cat, wh + OFF_W3, bo1, bo1, FFD, nullptr, hid,
        FFD, CATD, CATD, FFD, 1, 0, 0, 0, 0);

    // #7: L4: out[24576,768] = hid @ wo2^T (fp32)
    gemm16_kernel<<<dim3(Dsz/128, NTOK/128, 1), 256, SMEM_DYN>>>(
        hid, wh + OFF_W4, bo2, bo2, Dsz, out, nullptr,
        Dsz, FFD, FFD, Dsz, 0, 0, 0, 0, 0);
}

// round 11
// speedup vs baseline: 1.6409x; 1.3192x over previous
#include <cuda_runtime.h>
#include <cuda_fp16.h>
#include <cstdint>
#include <cstddef>

// Problem constants
#define Bsz 4
#define Lsz 512
#define Dsz 768
#define Wsz 12
#define Ksz (Lsz * Wsz)
#define NTOK (Bsz * Ksz)     // 24576
#define BLROWS (Bsz * Lsz)   // 2048
#define FFD 3072
#define CATD 1536

// fp16 weight buffer offsets (elements)
#define OFF_W1A 0u
#define OFF_W1B 2359296u
#define OFF_W2A 4718592u
#define OFF_W2B 7077888u
#define OFF_W3  9437184u
#define OFF_W4  14155776u
#define WTOT    16515072u

// Static device scratch (allocation-free rule)
__device__ alignas(128) __half g_wh[WTOT];
__device__ alignas(128) __half g_h16[(size_t)BLROWS * Dsz];
__device__ alignas(128) __half g_hid[(size_t)NTOK * FFD];
__device__ alignas(128) __half g_cat[(size_t)NTOK * CATD];
__device__ alignas(128) float  g_se[(size_t)BLROWS * CATD];
__device__ int g_is64;

// ---------------------------------------------------------------------------
// span_idx dtype detection (int64 vs int32)
// ---------------------------------------------------------------------------
__global__ void detect_idx_kernel(const unsigned int* __restrict__ sp, int nhalf) {
    __shared__ int s_any;
    if (threadIdx.x == 0) s_any = 0;
    __syncthreads();
    int found = 0;
    for (int i = threadIdx.x; i < nhalf; i += blockDim.x)
        if (sp[2 * i + 1] != 0u) found = 1;
    if (found) atomicOr(&s_any, 1);
    __syncthreads();
    if (threadIdx.x == 0) g_is64 = (s_any == 0) ? 1 : 0;
}

// ---------------------------------------------------------------------------
// Fused prep: h + all 6 weights fp32 -> fp16 in ONE launch
// ---------------------------------------------------------------------------
#define QC0 393216u
#define QC1 983040u
#define QC2 1572864u
#define QC3 2162688u
#define QC4 2752512u
#define QC5 3932160u
#define QC6 4521984u
#define PREP_BLOCKS ((QC6 + 255u) / 256u)

__global__ void prep_kernel(const float* __restrict__ h,
                            const float* __restrict__ ws1, const float* __restrict__ we1,
                            const float* __restrict__ ws2, const float* __restrict__ we2,
                            const float* __restrict__ wo1, const float* __restrict__ wo2,
                            __half* __restrict__ h16, __half* __restrict__ wh)
{
    unsigned int t = blockIdx.x * 256u + threadIdx.x;
    if (t >= QC6) return;
    const float* src;
    __half* dst;
    unsigned int off;
    if (t < QC0)      { src = h;   dst = h16;          off = t; }
    else if (t < QC1) { src = ws1; dst = wh + OFF_W1A; off = t - QC0; }
    else if (t < QC2) { src = we1; dst = wh + OFF_W1B; off = t - QC1; }
    else if (t < QC3) { src = ws2; dst = wh + OFF_W2A; off = t - QC2; }
    else if (t < QC4) { src = we2; dst = wh + OFF_W2B; off = t - QC3; }
    else if (t < QC5) { src = wo1; dst = wh + OFF_W3;  off = t - QC4; }
    else              { src = wo2; dst = wh + OFF_W4;  off = t - QC5; }
    float4 v = ((const float4*)src)[off];
    __half hh[4] = {__float2half_rn(v.x), __float2half_rn(v.y),
                    __float2half_rn(v.z), __float2half_rn(v.w)};
    ((uint2*)dst)[off] = *(uint2*)hh;
}

// ---------------------------------------------------------------------------
// PTX helpers
// ---------------------------------------------------------------------------
__device__ __forceinline__ uint32_t smem_u32(const void* p) {
    return (uint32_t)__cvta_generic_to_shared(p);
}
__device__ __forceinline__ void ldm_x4(uint32_t* r, uint32_t addr) {
    asm volatile("ldmatrix.sync.aligned.m8n8.x4.shared.b16 {%0,%1,%2,%3}, [%4];"
                 : "=r"(r[0]), "=r"(r[1]), "=r"(r[2]), "=r"(r[3]) : "r"(addr));
}
__device__ __forceinline__ void mma_f16(float* d, const uint32_t* a, const uint32_t* b) {
    asm volatile(
        "mma.sync.aligned.m16n8k16.row.col.f32.f16.f16.f32 "
        "{%0,%1,%2,%3},{%4,%5,%6,%7},{%8,%9},{%0,%1,%2,%3};"
        : "+f"(d[0]), "+f"(d[1]), "+f"(d[2]), "+f"(d[3])
        : "r"(a[0]), "r"(a[1]), "r"(a[2]), "r"(a[3]), "r"(b[0]), "r"(b[1]));
}
__device__ __forceinline__ void cp16(uint32_t dst, const void* src) {
    asm volatile("cp.async.cg.shared.global [%0], [%1], 16;" :: "r"(dst), "l"(src));
}

// ---------------------------------------------------------------------------
// fp16 tensor GEMM (NT): C = A*B^T + bias, opt ReLU. fp32 accumulate.
// Block 128xBNx32. BN=256: warp tile 64x64 (2x4), 1 CTA/SM, low smem B/MAC.
// BN=128: warp tile 64x32, 2 CTAs/SM (small-N layers).
// 3-stage cp.async. z batching; zBias: per-z bias; else col-split at nsplit.
// mode 0: fp32 C. mode 1: relu + fp16 C.
// ---------------------------------------------------------------------------
template<int BN>
__global__ __launch_bounds__(256, (BN == 128) ? 2 : 1)
void gemm16_kernel(const __half* __restrict__ A,
                   const __half* __restrict__ B,
                   const float* __restrict__ bias1,
                   const float* __restrict__ bias2, int nsplit,
                   float* __restrict__ Cf,
                   __half* __restrict__ Ch,
                   int N, int K, int lda, int ldc, int mode,
                   int zAoff, int zBoff, int zCoff, int zBias)
{
    constexpr int WN    = BN / 4;          // 64 or 32
    constexpr int NF    = WN / 8;          // 8 or 4
    constexpr int NP    = WN / 16;         // 4 or 2
    constexpr int TILEA = 128 * 80;        // 10240
    constexpr int TILEB = BN * 80;
    constexpr int STAGE = TILEA + TILEB;

    extern __shared__ char smem[];
    const uint32_t sbase = smem_u32(smem);

    const int tid  = threadIdx.x;
    const int lane = tid & 31;
    const int wid  = tid >> 5;
    const int wm   = (wid >> 2) * 64;
    const int wn   = (wid & 3) * WN;
    const int bm   = blockIdx.y << 7;
    const int bn   = blockIdx.x * BN;
    const int z    = blockIdx.z;

    const __half* aSrc = A + (size_t)z * zAoff + (size_t)bm * lda;
    const __half* bSrc = B + (size_t)z * zBoff + (size_t)bn * K;

    float acc[4][NF][4];
#pragma unroll
    for (int i = 0; i < 4; i++)
#pragma unroll
        for (int j = 0; j < NF; j++)
#pragma unroll
            for (int r = 0; r < 4; r++) acc[i][j][r] = 0.f;

    const int nk = K >> 5;

    auto issue = [&](int kt) {
        const uint32_t st = sbase + (kt % 3) * STAGE;
        const int kb = kt << 5;
#pragma unroll
        for (int i = 0; i < 2; i++) {              // A: 512 chunks
            const int c   = tid + 256 * i;
            const int row = c >> 2;
            const int ch  = c & 3;
            cp16(st + (uint32_t)row * 80 + ch * 16,
                 aSrc + (size_t)row * lda + kb + ch * 8);
        }
#pragma unroll
        for (int i = 0; i < BN / 64; i++) {        // B: BN*4 chunks
            const int c   = tid + 256 * i;
            const int row = c >> 2;
            const int ch  = c & 3;
            cp16(st + TILEA + (uint32_t)row * 80 + ch * 16,
                 bSrc + (size_t)row * K + kb + ch * 8);
        }
    };

    // ldmatrix lane mapping
    const int aq    = lane >> 3;
    const int arow  = ((aq & 1) << 3) + (lane & 7);
    const int acol  = (aq >> 1) << 3;
    const int brow4 = ((lane >> 4) << 3) + (lane & 7);
    const int bcol4 = ((lane >> 3) & 1) << 3;

    issue(0);
    asm volatile("cp.async.commit_group;" ::: "memory");
    issue(1);
    asm volatile("cp.async.commit_group;" ::: "memory");

    for (int kt = 0; kt < nk; kt++) {
        asm volatile("cp.async.wait_group 1;" ::: "memory");
        __syncthreads();
        if (kt + 2 < nk) issue(kt + 2);
        asm volatile("cp.async.commit_group;" ::: "memory");

        const uint32_t st = sbase + (kt % 3) * STAGE;

#pragma unroll
        for (int kk = 0; kk < 32; kk += 16) {
            uint32_t a[4][4], bb[NP][4];
#pragma unroll
            for (int mi = 0; mi < 4; mi++) {
                const uint32_t off = (uint32_t)(wm + mi * 16 + arow) * 80 + (kk + acol) * 2;
                ldm_x4(a[mi], st + off);
            }
#pragma unroll
            for (int p = 0; p < NP; p++) {
                const uint32_t off = (uint32_t)(wn + p * 16 + brow4) * 80 + (kk + bcol4) * 2;
                ldm_x4(bb[p], st + TILEA + off);
            }
#pragma unroll
            for (int mi = 0; mi < 4; mi++)
#pragma unroll
                for (int p = 0; p < NP; p++) {
                    mma_f16(acc[mi][2 * p],     a[mi], &bb[p][0]);
                    mma_f16(acc[mi][2 * p + 1], a[mi], &bb[p][2]);
                }
        }
    }

    // Epilogue
    float* Cfz = Cf ? Cf + (size_t)z * zCoff : nullptr;
    __half* Chz = Ch ? Ch + (size_t)z * zCoff : nullptr;
    const float* bA = (zBias && z) ? bias2 : bias1;

    const int lr = lane >> 2;
    const int lc = (lane & 3) * 2;
#pragma unroll
    for (int mi = 0; mi < 4; mi++) {
#pragma unroll
        for (int ni = 0; ni < NF; ni++) {
            const int gm = bm + wm + mi * 16 + lr;
            const int gc = bn + wn + ni * 8 + lc;
            const float b0 = (gc < nsplit)     ? bA[gc]     : bias2[gc - nsplit];
            const float b1 = (gc + 1 < nsplit) ? bA[gc + 1] : bias2[gc + 1 - nsplit];
            float v0 = acc[mi][ni][0] + b0;
            float v1 = acc[mi][ni][1] + b1;
            float v2 = acc[mi][ni][2] + b0;
            float v3 = acc[mi][ni][3] + b1;
            if (mode == 0) {
                *(float2*)(Cfz + (size_t)gm * ldc + gc)       = make_float2(v0, v1);
                *(float2*)(Cfz + (size_t)(gm + 8) * ldc + gc) = make_float2(v2, v3);
            } else {
                v0 = fmaxf(v0, 0.f); v1 = fmaxf(v1, 0.f);
                v2 = fmaxf(v2, 0.f); v3 = fmaxf(v3, 0.f);
                __half p01[2] = {__float2half_rn(v0), __float2half_rn(v1)};
                __half p23[2] = {__float2half_rn(v2), __float2half_rn(v3)};
                *(uint32_t*)(Chz + (size_t)gm * ldc + gc)       = *(uint32_t*)p01;
                *(uint32_t*)(Chz + (size_t)(gm + 8) * ldc + gc) = *(uint32_t*)p23;
            }
        }
    }
}

// ---------------------------------------------------------------------------
// Gather spans from combined se[2048,1536], ReLU, fp16 -> cat [NTOK, 1536]
// ---------------------------------------------------------------------------
__global__ void gather_cat_kernel(const float* __restrict__ se,
                                  const void* __restrict__ span,
                                  __half* __restrict__ cat)
{
    const int QD = CATD / 4;
    int t = blockIdx.x * blockDim.x + threadIdx.x;
    if (t >= NTOK * QD) return;
    int r = t / QD;
    int q = t - r * QD;
    int b = r / Ksz;
    int col = q * 4;

    int which = (col < Dsz) ? 0 : 1;
    size_t pos = (size_t)r * 2 + which;
    long long idx;
    if (g_is64) idx = ((const long long*)span)[pos];
    else        idx = (long long)((const int*)span)[pos];

    const float* src = se + ((size_t)b * Lsz + idx) * CATD + col;

    float4 v = *(const float4*)src;
    v.x = fmaxf(v.x, 0.f); v.y = fmaxf(v.y, 0.f);
    v.z = fmaxf(v.z, 0.f); v.w = fmaxf(v.w, 0.f);

    __half hh[4] = {__float2half_rn(v.x), __float2half_rn(v.y),
                    __float2half_rn(v.z), __float2half_rn(v.w)};
    ((uint2*)cat)[t] = *(uint2*)hh;
}

// ---------------------------------------------------------------------------
// Launch (#6 = L3 GEMM for ncu -s 5 -c 1)
// ---------------------------------------------------------------------------
extern "C" void kernel_launch(void* const* d_in, const int* in_sizes, int n_in,
                              void* d_out, int out_size)
{
    const float* h   = (const float*)d_in[0];
    const void*  sp  = d_in[1];
    const float* ws1 = (const float*)d_in[2];
    const float* bs1 = (const float*)d_in[3];
    const float* ws2 = (const float*)d_in[4];
    const float* bs2 = (const float*)d_in[5];
    const float* we1 = (const float*)d_in[6];
    const float* be1 = (const float*)d_in[7];
    const float* we2 = (const float*)d_in[8];
    const float* be2 = (const float*)d_in[9];
    const float* wo1 = (const float*)d_in[10];
    const float* bo1 = (const float*)d_in[11];
    const float* wo2 = (const float*)d_in[12];
    const float* bo2 = (const float*)d_in[13];
    float* out = (float*)d_out;

    __half *wh, *h16, *hid, *cat;
    float *se;
    cudaGetSymbolAddress((void**)&wh,  g_wh);
    cudaGetSymbolAddress((void**)&h16, g_h16);
    cudaGetSymbolAddress((void**)&hid, g_hid);
    cudaGetSymbolAddress((void**)&cat, g_cat);
    cudaGetSymbolAddress((void**)&se,  g_se);

    const int SM256 = 3 * (128 * 80 + 256 * 80);   // 92160
    const int SM128 = 3 * (128 * 80 + 128 * 80);   // 61440
    cudaFuncSetAttribute(gemm16_kernel<256>,
                         cudaFuncAttributeMaxDynamicSharedMemorySize, SM256);
    cudaFuncSetAttribute(gemm16_kernel<128>,
                         cudaFuncAttributeMaxDynamicSharedMemorySize, SM128);

    // #1
    detect_idx_kernel<<<1, 256>>>((const unsigned int*)sp, NTOK);

    // #2
    prep_kernel<<<PREP_BLOCKS, 256>>>(h, ws1, we1, ws2, we2, wo1, wo2, h16, wh);

    // #3: L1 fused start|end layer1: hid[2048,6144] = h @ [ws1;we1]^T, relu
    gemm16_kernel<256><<<dim3(6144/256, BLROWS/128, 1), 256, SM256>>>(
        h16, wh + OFF_W1A, bs1, be1, FFD, nullptr, hid,
        6144, Dsz, Dsz, 6144, 1, 0, 0, 0, 0);

    // #4: L2 batched (z=0: start, z=1: end)
    gemm16_kernel<128><<<dim3(Dsz/128, BLROWS/128, 2), 256, SM128>>>(
        hid, wh + OFF_W2A, bs2, be2, Dsz, se, nullptr,
        Dsz, FFD, 6144, CATD, 0, FFD, (int)(OFF_W2B - OFF_W2A), Dsz, 1);

    // #5: gather + concat + relu -> fp16 cat
    int gthreads = NTOK * (CATD / 4);
    gather_cat_kernel<<<(gthreads + 255) / 256, 256>>>(se, sp, cat);

    // #6: L3 (dominant): hid[24576,3072] = cat @ wo1^T, relu
    gemm16_kernel<256><<<dim3(FFD/256, NTOK/128, 1), 256, SM256>>>(
        cat, wh + OFF_W3, bo1, bo1, FFD, nullptr, hid,
        FFD, CATD, CATD, FFD, 1, 0, 0, 0, 0);

    // #7: L4: out[24576,768] = hid @ wo2^T (fp32)
    gemm16_kernel<256><<<dim3(Dsz/256, NTOK/128, 1), 256, SM256>>>(
        hid, wh + OFF_W4, bo2, bo2, Dsz, out, nullptr,
        Dsz, FFD, FFD, Dsz, 0, 0, 0, 0, 0);
}

// round 12
// speedup vs baseline: 1.7190x; 1.0476x over previous
#include <cuda_runtime.h>
#include <cuda_fp16.h>
#include <cstdint>
#include <cstddef>

// Problem constants
#define Bsz 4
#define Lsz 512
#define Dsz 768
#define Wsz 12
#define Ksz (Lsz * Wsz)
#define NTOK (Bsz * Ksz)     // 24576
#define BLROWS (Bsz * Lsz)   // 2048
#define FFD 3072
#define CATD 1536

// fp16 weight buffer offsets (elements)
#define OFF_W1A 0u
#define OFF_W1B 2359296u
#define OFF_W2A 4718592u
#define OFF_W2B 7077888u
#define OFF_W3  9437184u
#define OFF_W4  14155776u
#define WTOT    16515072u

// Static device scratch (allocation-free rule)
__device__ alignas(128) __half g_wh[WTOT];
__device__ alignas(128) __half g_h16[(size_t)BLROWS * Dsz];
__device__ alignas(128) __half g_hid[(size_t)NTOK * FFD];
__device__ alignas(128) __half g_cat[(size_t)NTOK * CATD];
__device__ alignas(128) __half g_se16[(size_t)BLROWS * CATD];
__device__ int g_is64;

// ---------------------------------------------------------------------------
// span_idx dtype detection (int64 vs int32)
// ---------------------------------------------------------------------------
__global__ void detect_idx_kernel(const unsigned int* __restrict__ sp, int nhalf) {
    __shared__ int s_any;
    if (threadIdx.x == 0) s_any = 0;
    __syncthreads();
    int found = 0;
    for (int i = threadIdx.x; i < nhalf; i += blockDim.x)
        if (sp[2 * i + 1] != 0u) found = 1;
    if (found) atomicOr(&s_any, 1);
    __syncthreads();
    if (threadIdx.x == 0) g_is64 = (s_any == 0) ? 1 : 0;
}

// ---------------------------------------------------------------------------
// Fused prep: h + all 6 weights fp32 -> fp16 in ONE launch
// ---------------------------------------------------------------------------
#define QC0 393216u
#define QC1 983040u
#define QC2 1572864u
#define QC3 2162688u
#define QC4 2752512u
#define QC5 3932160u
#define QC6 4521984u
#define PREP_BLOCKS ((QC6 + 255u) / 256u)

__global__ void prep_kernel(const float* __restrict__ h,
                            const float* __restrict__ ws1, const float* __restrict__ we1,
                            const float* __restrict__ ws2, const float* __restrict__ we2,
                            const float* __restrict__ wo1, const float* __restrict__ wo2,
                            __half* __restrict__ h16, __half* __restrict__ wh)
{
    unsigned int t = blockIdx.x * 256u + threadIdx.x;
    if (t >= QC6) return;
    const float* src;
    __half* dst;
    unsigned int off;
    if (t < QC0)      { src = h;   dst = h16;          off = t; }
    else if (t < QC1) { src = ws1; dst = wh + OFF_W1A; off = t - QC0; }
    else if (t < QC2) { src = we1; dst = wh + OFF_W1B; off = t - QC1; }
    else if (t < QC3) { src = ws2; dst = wh + OFF_W2A; off = t - QC2; }
    else if (t < QC4) { src = we2; dst = wh + OFF_W2B; off = t - QC3; }
    else if (t < QC5) { src = wo1; dst = wh + OFF_W3;  off = t - QC4; }
    else              { src = wo2; dst = wh + OFF_W4;  off = t - QC5; }
    float4 v = ((const float4*)src)[off];
    __half hh[4] = {__float2half_rn(v.x), __float2half_rn(v.y),
                    __float2half_rn(v.z), __float2half_rn(v.w)};
    ((uint2*)dst)[off] = *(uint2*)hh;
}

// ---------------------------------------------------------------------------
// PTX helpers
// ---------------------------------------------------------------------------
__device__ __forceinline__ uint32_t smem_u32(const void* p) {
    return (uint32_t)__cvta_generic_to_shared(p);
}
__device__ __forceinline__ void ldm_x4(uint32_t* r, uint32_t addr) {
    asm volatile("ldmatrix.sync.aligned.m8n8.x4.shared.b16 {%0,%1,%2,%3}, [%4];"
                 : "=r"(r[0]), "=r"(r[1]), "=r"(r[2]), "=r"(r[3]) : "r"(addr));
}
__device__ __forceinline__ void mma_f16(float* d, const uint32_t* a, const uint32_t* b) {
    asm volatile(
        "mma.sync.aligned.m16n8k16.row.col.f32.f16.f16.f32 "
        "{%0,%1,%2,%3},{%4,%5,%6,%7},{%8,%9},{%0,%1,%2,%3};"
        : "+f"(d[0]), "+f"(d[1]), "+f"(d[2]), "+f"(d[3])
        : "r"(a[0]), "r"(a[1]), "r"(a[2]), "r"(a[3]), "r"(b[0]), "r"(b[1]));
}
__device__ __forceinline__ void cp16(uint32_t dst, const void* src) {
    asm volatile("cp.async.cg.shared.global [%0], [%1], 16;" :: "r"(dst), "l"(src));
}

// ---------------------------------------------------------------------------
// fp16 tensor GEMM (NT): C = A*B^T + bias, fp32 accumulate.
// BN=256/NTHR=512: warp tile 32x64 (4x4 warps), 16 warps/SM, 1 CTA/SM.
// BN=128/NTHR=256: warp tile 64x32 (2x4 warps), 2 CTAs/SM (small-N layers).
// 3-stage cp.async. z batching; zBias: per-z bias; else col-split at nsplit.
// mode 0: fp32 C. mode 1: relu + fp16 C. mode 2: fp16 C (no relu).
// ---------------------------------------------------------------------------
template<int BN, int NTHR>
__global__ __launch_bounds__(NTHR, (BN == 128) ? 2 : 1)
void gemm16_kernel(const __half* __restrict__ A,
                   const __half* __restrict__ B,
                   const float* __restrict__ bias1,
                   const float* __restrict__ bias2, int nsplit,
                   float* __restrict__ Cf,
                   __half* __restrict__ Ch,
                   int N, int K, int lda, int ldc, int mode,
                   int zAoff, int zBoff, int zCoff, int zBias)
{
    constexpr int NWARP = NTHR / 32;
    constexpr int WM    = 128 / (NWARP / 4);   // 32 (big) or 64 (small)
    constexpr int WN    = BN / 4;              // 64 or 32
    constexpr int MI    = WM / 16;             // 2 or 4
    constexpr int NP    = WN / 16;             // 4 or 2
    constexpr int NF    = WN / 8;              // 8 or 4
    constexpr int TILEA = 128 * 80;
    constexpr int TILEB = BN * 80;
    constexpr int STAGE = TILEA + TILEB;

    extern __shared__ char smem[];
    const uint32_t sbase = smem_u32(smem);

    const int tid  = threadIdx.x;
    const int lane = tid & 31;
    const int wid  = tid >> 5;
    const int wm   = (wid >> 2) * WM;
    const int wn   = (wid & 3) * WN;
    const int bm   = blockIdx.y << 7;
    const int bn   = blockIdx.x * BN;
    const int z    = blockIdx.z;

    const __half* aSrc = A + (size_t)z * zAoff + (size_t)bm * lda;
    const __half* bSrc = B + (size_t)z * zBoff + (size_t)bn * K;

    float acc[MI][NF][4];
#pragma unroll
    for (int i = 0; i < MI; i++)
#pragma unroll
        for (int j = 0; j < NF; j++)
#pragma unroll
            for (int r = 0; r < 4; r++) acc[i][j][r] = 0.f;

    const int nk = K >> 5;

    auto issue = [&](int kt) {
        const uint32_t st = sbase + (kt % 3) * STAGE;
        const int kb = kt << 5;
#pragma unroll
        for (int c = tid; c < 512; c += NTHR) {
            const int row = c >> 2, ch = c & 3;
            cp16(st + (uint32_t)row * 80 + ch * 16,
                 aSrc + (size_t)row * lda + kb + ch * 8);
        }
#pragma unroll
        for (int c = tid; c < BN * 4; c += NTHR) {
            const int row = c >> 2, ch = c & 3;
            cp16(st + TILEA + (uint32_t)row * 80 + ch * 16,
                 bSrc + (size_t)row * K + kb + ch * 8);
        }
    };

    // ldmatrix lane mapping
    const int aq    = lane >> 3;
    const int arow  = ((aq & 1) << 3) + (lane & 7);
    const int acol  = (aq >> 1) << 3;
    const int brow4 = ((lane >> 4) << 3) + (lane & 7);
    const int bcol4 = ((lane >> 3) & 1) << 3;

    issue(0);
    asm volatile("cp.async.commit_group;" ::: "memory");
    issue(1);
    asm volatile("cp.async.commit_group;" ::: "memory");

    for (int kt = 0; kt < nk; kt++) {
        asm volatile("cp.async.wait_group 1;" ::: "memory");
        __syncthreads();
        if (kt + 2 < nk) issue(kt + 2);
        asm volatile("cp.async.commit_group;" ::: "memory");

        const uint32_t st = sbase + (kt % 3) * STAGE;

#pragma unroll
        for (int kk = 0; kk < 32; kk += 16) {
            uint32_t a[MI][4], bb[NP][4];
#pragma unroll
            for (int mi = 0; mi < MI; mi++) {
                const uint32_t off = (uint32_t)(wm + mi * 16 + arow) * 80 + (kk + acol) * 2;
                ldm_x4(a[mi], st + off);
            }
#pragma unroll
            for (int p = 0; p < NP; p++) {
                const uint32_t off = (uint32_t)(wn + p * 16 + brow4) * 80 + (kk + bcol4) * 2;
                ldm_x4(bb[p], st + TILEA + off);
            }
#pragma unroll
            for (int mi = 0; mi < MI; mi++)
#pragma unroll
                for (int p = 0; p < NP; p++) {
                    mma_f16(acc[mi][2 * p],     a[mi], &bb[p][0]);
                    mma_f16(acc[mi][2 * p + 1], a[mi], &bb[p][2]);
                }
        }
    }

    // Epilogue
    float* Cfz = Cf ? Cf + (size_t)z * zCoff : nullptr;
    __half* Chz = Ch ? Ch + (size_t)z * zCoff : nullptr;
    const float* bA = (zBias && z) ? bias2 : bias1;

    const int lr = lane >> 2;
    const int lc = (lane & 3) * 2;
#pragma unroll
    for (int mi = 0; mi < MI; mi++) {
#pragma unroll
        for (int ni = 0; ni < NF; ni++) {
            const int gm = bm + wm + mi * 16 + lr;
            const int gc = bn + wn + ni * 8 + lc;
            const float b0 = (gc < nsplit)     ? bA[gc]     : bias2[gc - nsplit];
            const float b1 = (gc + 1 < nsplit) ? bA[gc + 1] : bias2[gc + 1 - nsplit];
            float v0 = acc[mi][ni][0] + b0;
            float v1 = acc[mi][ni][1] + b1;
            float v2 = acc[mi][ni][2] + b0;
            float v3 = acc[mi][ni][3] + b1;
            if (mode == 0) {
                *(float2*)(Cfz + (size_t)gm * ldc + gc)       = make_float2(v0, v1);
                *(float2*)(Cfz + (size_t)(gm + 8) * ldc + gc) = make_float2(v2, v3);
            } else {
                if (mode == 1) {
                    v0 = fmaxf(v0, 0.f); v1 = fmaxf(v1, 0.f);
                    v2 = fmaxf(v2, 0.f); v3 = fmaxf(v3, 0.f);
                }
                __half p01[2] = {__float2half_rn(v0), __float2half_rn(v1)};
                __half p23[2] = {__float2half_rn(v2), __float2half_rn(v3)};
                *(uint32_t*)(Chz + (size_t)gm * ldc + gc)       = *(uint32_t*)p01;
                *(uint32_t*)(Chz + (size_t)(gm + 8) * ldc + gc) = *(uint32_t*)p23;
            }
        }
    }
}

// ---------------------------------------------------------------------------
// Gather spans from fp16 se[2048,1536], ReLU -> cat [NTOK, 1536] (fp16)
// One thread per 8-half (16B) chunk. relu(fp16(x)) == fp16(relu(x)).
// ---------------------------------------------------------------------------
__global__ void gather_cat_kernel(const __half* __restrict__ se,
                                  const void* __restrict__ span,
                                  __half* __restrict__ cat)
{
    const int QD = CATD / 8;   // 192 chunks per row
    int t = blockIdx.x * blockDim.x + threadIdx.x;
    if (t >= NTOK * QD) return;
    int r = t / QD;
    int q = t - r * QD;
    int b = r / Ksz;
    int col = q * 8;

    int which = (col < Dsz) ? 0 : 1;
    size_t pos = (size_t)r * 2 + which;
    long long idx;
    if (g_is64) idx = ((const long long*)span)[pos];
    else        idx = (long long)((const int*)span)[pos];

    const __half* src = se + ((size_t)b * Lsz + idx) * CATD + col;
    uint4 v = *(const uint4*)src;

    const __half2 z2 = __float2half2_rn(0.f);
    __half2* h = (__half2*)&v;
#pragma unroll
    for (int i = 0; i < 4; i++) h[i] = __hmax2(h[i], z2);

    ((uint4*)cat)[t] = v;
}

// ---------------------------------------------------------------------------
// Launch (#6 = L3 GEMM for ncu -s 5 -c 1)
// ---------------------------------------------------------------------------
extern "C" void kernel_launch(void* const* d_in, const int* in_sizes, int n_in,
                              void* d_out, int out_size)
{
    const float* h   = (const float*)d_in[0];
    const void*  sp  = d_in[1];
    const float* ws1 = (const float*)d_in[2];
    const float* bs1 = (const float*)d_in[3];
    const float* ws2 = (const float*)d_in[4];
    const float* bs2 = (const float*)d_in[5];
    const float* we1 = (const float*)d_in[6];
    const float* be1 = (const float*)d_in[7];
    const float* we2 = (const float*)d_in[8];
    const float* be2 = (const float*)d_in[9];
    const float* wo1 = (const float*)d_in[10];
    const float* bo1 = (const float*)d_in[11];
    const float* wo2 = (const float*)d_in[12];
    const float* bo2 = (const float*)d_in[13];
    float* out = (float*)d_out;

    __half *wh, *h16, *hid, *cat, *se;
    cudaGetSymbolAddress((void**)&wh,  g_wh);
    cudaGetSymbolAddress((void**)&h16, g_h16);
    cudaGetSymbolAddress((void**)&hid, g_hid);
    cudaGetSymbolAddress((void**)&cat, g_cat);
    cudaGetSymbolAddress((void**)&se,  g_se16);

    const int SM256 = 3 * (128 * 80 + 256 * 80);   // 92160
    const int SM128 = 3 * (128 * 80 + 128 * 80);   // 61440
    cudaFuncSetAttribute((const void*)gemm16_kernel<256, 512>,
                         cudaFuncAttributeMaxDynamicSharedMemorySize, SM256);
    cudaFuncSetAttribute((const void*)gemm16_kernel<128, 256>,
                         cudaFuncAttributeMaxDynamicSharedMemorySize, SM128);

    // #1
    detect_idx_kernel<<<1, 256>>>((const unsigned int*)sp, NTOK);

    // #2
    prep_kernel<<<PREP_BLOCKS, 256>>>(h, ws1, we1, ws2, we2, wo1, wo2, h16, wh);

    // #3: L1 fused start|end layer1: hid[2048,6144] = h @ [ws1;we1]^T, relu
    gemm16_kernel<256, 512><<<dim3(6144/256, BLROWS/128, 1), 512, SM256>>>(
        h16, wh + OFF_W1A, bs1, be1, FFD, nullptr, hid,
        6144, Dsz, Dsz, 6144, 1, 0, 0, 0, 0);

    // #4: L2 batched (z=0: start, z=1: end) -> se fp16 (no relu; relu in gather)
    gemm16_kernel<128, 256><<<dim3(Dsz/128, BLROWS/128, 2), 256, SM128>>>(
        hid, wh + OFF_W2A, bs2, be2, Dsz, nullptr, se,
        Dsz, FFD, 6144, CATD, 2, FFD, (int)(OFF_W2B - OFF_W2A), Dsz, 1);

    // #5: gather + relu -> fp16 cat
    int gthreads = NTOK * (CATD / 8);
    gather_cat_kernel<<<(gthreads + 255) / 256, 256>>>(se, sp, cat);

    // #6: L3 (dominant): hid[24576,3072] = cat @ wo1^T, relu
    gemm16_kernel<256, 512><<<dim3(FFD/256, NTOK/128, 1), 512, SM256>>>(
        cat, wh + OFF_W3, bo1, bo1, FFD, nullptr, hid,
        FFD, CATD, CATD, FFD, 1, 0, 0, 0, 0);

    // #7: L4: out[24576,768] = hid @ wo2^T (fp32)
    gemm16_kernel<256, 512><<<dim3(Dsz/256, NTOK/128, 1), 512, SM256>>>(
        hid, wh + OFF_W4, bo2, bo2, Dsz, out, nullptr,
        Dsz, FFD, FFD, Dsz, 0, 0, 0, 0, 0);
}

// round 13
// speedup vs baseline: 1.8447x; 1.0731x over previous
#include <cuda_runtime.h>
#include <cuda_fp16.h>
#include <cstdint>
#include <cstddef>

// Problem constants
#define Bsz 4
#define Lsz 512
#define Dsz 768
#define Wsz 12
#define Ksz (Lsz * Wsz)
#define NTOK (Bsz * Ksz)     // 24576
#define BLROWS (Bsz * Lsz)   // 2048
#define FFD 3072
#define CATD 1536

// fp16 weight buffer offsets (elements)
#define OFF_W1A 0u
#define OFF_W1B 2359296u
#define OFF_W2A 4718592u
#define OFF_W2B 7077888u
#define OFF_W3  9437184u
#define OFF_W4  14155776u
#define WTOT    16515072u

// Static device scratch (allocation-free rule)
__device__ alignas(128) __half g_wh[WTOT];
__device__ alignas(128) __half g_h16[(size_t)BLROWS * Dsz];
__device__ alignas(128) __half g_hid[(size_t)NTOK * FFD];
__device__ alignas(128) __half g_cat[(size_t)NTOK * CATD];
__device__ alignas(128) __half g_se16[(size_t)BLROWS * CATD];
__device__ int g_is64;

// ---------------------------------------------------------------------------
// span_idx dtype detection (int64 vs int32)
// ---------------------------------------------------------------------------
__global__ void detect_idx_kernel(const unsigned int* __restrict__ sp, int nhalf) {
    __shared__ int s_any;
    if (threadIdx.x == 0) s_any = 0;
    __syncthreads();
    int found = 0;
    for (int i = threadIdx.x; i < nhalf; i += blockDim.x)
        if (sp[2 * i + 1] != 0u) found = 1;
    if (found) atomicOr(&s_any, 1);
    __syncthreads();
    if (threadIdx.x == 0) g_is64 = (s_any == 0) ? 1 : 0;
}

// ---------------------------------------------------------------------------
// Fused prep: h + all 6 weights fp32 -> fp16 in ONE launch
// ---------------------------------------------------------------------------
#define QC0 393216u
#define QC1 983040u
#define QC2 1572864u
#define QC3 2162688u
#define QC4 2752512u
#define QC5 3932160u
#define QC6 4521984u
#define PREP_BLOCKS ((QC6 + 255u) / 256u)

__global__ void prep_kernel(const float* __restrict__ h,
                            const float* __restrict__ ws1, const float* __restrict__ we1,
                            const float* __restrict__ ws2, const float* __restrict__ we2,
                            const float* __restrict__ wo1, const float* __restrict__ wo2,
                            __half* __restrict__ h16, __half* __restrict__ wh)
{
    unsigned int t = blockIdx.x * 256u + threadIdx.x;
    if (t >= QC6) return;
    const float* src;
    __half* dst;
    unsigned int off;
    if (t < QC0)      { src = h;   dst = h16;          off = t; }
    else if (t < QC1) { src = ws1; dst = wh + OFF_W1A; off = t - QC0; }
    else if (t < QC2) { src = we1; dst = wh + OFF_W1B; off = t - QC1; }
    else if (t < QC3) { src = ws2; dst = wh + OFF_W2A; off = t - QC2; }
    else if (t < QC4) { src = we2; dst = wh + OFF_W2B; off = t - QC3; }
    else if (t < QC5) { src = wo1; dst = wh + OFF_W3;  off = t - QC4; }
    else              { src = wo2; dst = wh + OFF_W4;  off = t - QC5; }
    float4 v = ((const float4*)src)[off];
    __half hh[4] = {__float2half_rn(v.x), __float2half_rn(v.y),
                    __float2half_rn(v.z), __float2half_rn(v.w)};
    ((uint2*)dst)[off] = *(uint2*)hh;
}

// ---------------------------------------------------------------------------
// PTX helpers
// ---------------------------------------------------------------------------
__device__ __forceinline__ uint32_t smem_u32(const void* p) {
    return (uint32_t)__cvta_generic_to_shared(p);
}
__device__ __forceinline__ void ldm_x4(uint32_t* r, uint32_t addr) {
    asm volatile("ldmatrix.sync.aligned.m8n8.x4.shared.b16 {%0,%1,%2,%3}, [%4];"
                 : "=r"(r[0]), "=r"(r[1]), "=r"(r[2]), "=r"(r[3]) : "r"(addr));
}
__device__ __forceinline__ void mma_f16(float* d, const uint32_t* a, const uint32_t* b) {
    asm volatile(
        "mma.sync.aligned.m16n8k16.row.col.f32.f16.f16.f32 "
        "{%0,%1,%2,%3},{%4,%5,%6,%7},{%8,%9},{%0,%1,%2,%3};"
        : "+f"(d[0]), "+f"(d[1]), "+f"(d[2]), "+f"(d[3])
        : "r"(a[0]), "r"(a[1]), "r"(a[2]), "r"(a[3]), "r"(b[0]), "r"(b[1]));
}
__device__ __forceinline__ void cp16(uint32_t dst, const void* src) {
    asm volatile("cp.async.cg.shared.global [%0], [%1], 16;" :: "r"(dst), "l"(src));
}

// ---------------------------------------------------------------------------
// fp16 tensor GEMM (NT): C = A*B^T + bias, fp32 accumulate. BK=64.
// BN=256/NTHR=512: warp tile 32x64 (4x4), 16 warps, 1 CTA/SM.
// BN=128/NTHR=256: warp tile 64x32 (2x4), 2 CTAs/SM.
// 3-stage cp.async + cross-kk FRAGMENT DOUBLE BUFFER (LDSM k+1 || MMA k).
// mode 0: fp32 C. mode 1: relu + fp16 C. mode 2: fp16 C (no relu).
// Requires M%128==0, N%BN==0, K%64==0.
// ---------------------------------------------------------------------------
#define SKB 144   // bytes per smem row: 128B data + 16B pad

template<int BN, int NTHR>
__global__ __launch_bounds__(NTHR, (BN == 128) ? 2 : 1)
void gemm16_kernel(const __half* __restrict__ A,
                   const __half* __restrict__ B,
                   const float* __restrict__ bias1,
                   const float* __restrict__ bias2, int nsplit,
                   float* __restrict__ Cf,
                   __half* __restrict__ Ch,
                   int N, int K, int lda, int ldc, int mode,
                   int zAoff, int zBoff, int zCoff, int zBias)
{
    constexpr int NWARP = NTHR / 32;
    constexpr int WM    = 128 / (NWARP / 4);   // 32 (big) or 64 (small)
    constexpr int WN    = BN / 4;              // 64 or 32
    constexpr int MI    = WM / 16;             // 2 or 4
    constexpr int NP    = WN / 16;             // 4 or 2
    constexpr int NF    = WN / 8;              // 8 or 4
    constexpr int TILEA = 128 * SKB;           // 18432
    constexpr int TILEB = BN * SKB;
    constexpr int STAGE = TILEA + TILEB;

    extern __shared__ char smem[];
    const uint32_t sbase = smem_u32(smem);

    const int tid  = threadIdx.x;
    const int lane = tid & 31;
    const int wid  = tid >> 5;
    const int wm   = (wid >> 2) * WM;
    const int wn   = (wid & 3) * WN;
    const int bm   = blockIdx.y << 7;
    const int bn   = blockIdx.x * BN;
    const int z    = blockIdx.z;

    const __half* aSrc = A + (size_t)z * zAoff + (size_t)bm * lda;
    const __half* bSrc = B + (size_t)z * zBoff + (size_t)bn * K;

    float acc[MI][NF][4];
#pragma unroll
    for (int i = 0; i < MI; i++)
#pragma unroll
        for (int j = 0; j < NF; j++)
#pragma unroll
            for (int r = 0; r < 4; r++) acc[i][j][r] = 0.f;

    const int nk = K >> 6;

    // cp.async: A 128 rows x 8 chunks + B BN rows x 8 chunks (16B each)
    auto issue = [&](int kt) {
        const uint32_t st = sbase + (kt % 3) * STAGE;
        const int kb = kt << 6;
#pragma unroll
        for (int c = tid; c < 1024; c += NTHR) {
            const int row = c >> 3, ch = c & 7;
            cp16(st + (uint32_t)row * SKB + ch * 16,
                 aSrc + (size_t)row * lda + kb + ch * 8);
        }
#pragma unroll
        for (int c = tid; c < BN * 8; c += NTHR) {
            const int row = c >> 3, ch = c & 7;
            cp16(st + TILEA + (uint32_t)row * SKB + ch * 16,
                 bSrc + (size_t)row * K + kb + ch * 8);
        }
    };

    // ldmatrix lane mapping
    const int aq    = lane >> 3;
    const int arow  = ((aq & 1) << 3) + (lane & 7);
    const int acol  = (aq >> 1) << 3;
    const int brow4 = ((lane >> 4) << 3) + (lane & 7);
    const int bcol4 = ((lane >> 3) & 1) << 3;

    uint32_t a[2][MI][4], bb[2][NP][4];

    auto ldfrag = [&](uint32_t st, int kk, int fb) {
#pragma unroll
        for (int mi = 0; mi < MI; mi++) {
            const uint32_t off = (uint32_t)(wm + mi * 16 + arow) * SKB + (kk + acol) * 2;
            ldm_x4(a[fb][mi], st + off);
        }
#pragma unroll
        for (int p = 0; p < NP; p++) {
            const uint32_t off = (uint32_t)(wn + p * 16 + brow4) * SKB + (kk + bcol4) * 2;
            ldm_x4(bb[fb][p], st + TILEA + off);
        }
    };

    issue(0);
    asm volatile("cp.async.commit_group;" ::: "memory");
    issue(1);
    asm volatile("cp.async.commit_group;" ::: "memory");

    for (int kt = 0; kt < nk; kt++) {
        asm volatile("cp.async.wait_group 1;" ::: "memory");
        __syncthreads();
        if (kt + 2 < nk) issue(kt + 2);
        asm volatile("cp.async.commit_group;" ::: "memory");

        const uint32_t st = sbase + (kt % 3) * STAGE;

        ldfrag(st, 0, 0);
#pragma unroll
        for (int j = 0; j < 4; j++) {
            const int cur = j & 1;
            if (j < 3) ldfrag(st, (j + 1) * 16, cur ^ 1);
#pragma unroll
            for (int mi = 0; mi < MI; mi++)
#pragma unroll
                for (int p = 0; p < NP; p++) {
                    mma_f16(acc[mi][2 * p],     a[cur][mi], &bb[cur][p][0]);
                    mma_f16(acc[mi][2 * p + 1], a[cur][mi], &bb[cur][p][2]);
                }
        }
    }

    // Epilogue
    float* Cfz = Cf ? Cf + (size_t)z * zCoff : nullptr;
    __half* Chz = Ch ? Ch + (size_t)z * zCoff : nullptr;
    const float* bA = (zBias && z) ? bias2 : bias1;

    const int lr = lane >> 2;
    const int lc = (lane & 3) * 2;
#pragma unroll
    for (int mi = 0; mi < MI; mi++) {
#pragma unroll
        for (int ni = 0; ni < NF; ni++) {
            const int gm = bm + wm + mi * 16 + lr;
            const int gc = bn + wn + ni * 8 + lc;
            const float b0 = (gc < nsplit)     ? bA[gc]     : bias2[gc - nsplit];
            const float b1 = (gc + 1 < nsplit) ? bA[gc + 1] : bias2[gc + 1 - nsplit];
            float v0 = acc[mi][ni][0] + b0;
            float v1 = acc[mi][ni][1] + b1;
            float v2 = acc[mi][ni][2] + b0;
            float v3 = acc[mi][ni][3] + b1;
            if (mode == 0) {
                *(float2*)(Cfz + (size_t)gm * ldc + gc)       = make_float2(v0, v1);
                *(float2*)(Cfz + (size_t)(gm + 8) * ldc + gc) = make_float2(v2, v3);
            } else {
                if (mode == 1) {
                    v0 = fmaxf(v0, 0.f); v1 = fmaxf(v1, 0.f);
                    v2 = fmaxf(v2, 0.f); v3 = fmaxf(v3, 0.f);
                }
                __half p01[2] = {__float2half_rn(v0), __float2half_rn(v1)};
                __half p23[2] = {__float2half_rn(v2), __float2half_rn(v3)};
                *(uint32_t*)(Chz + (size_t)gm * ldc + gc)       = *(uint32_t*)p01;
                *(uint32_t*)(Chz + (size_t)(gm + 8) * ldc + gc) = *(uint32_t*)p23;
            }
        }
    }
}

// ---------------------------------------------------------------------------
// Gather spans from fp16 se[2048,1536], ReLU -> cat [NTOK, 1536] (fp16)
// ---------------------------------------------------------------------------
__global__ void gather_cat_kernel(const __half* __restrict__ se,
                                  const void* __restrict__ span,
                                  __half* __restrict__ cat)
{
    const int QD = CATD / 8;
    int t = blockIdx.x * blockDim.x + threadIdx.x;
    if (t >= NTOK * QD) return;
    int r = t / QD;
    int q = t - r * QD;
    int b = r / Ksz;
    int col = q * 8;

    int which = (col < Dsz) ? 0 : 1;
    size_t pos = (size_t)r * 2 + which;
    long long idx;
    if (g_is64) idx = ((const long long*)span)[pos];
    else        idx = (long long)((const int*)span)[pos];

    const __half* src = se + ((size_t)b * Lsz + idx) * CATD + col;
    uint4 v = *(const uint4*)src;

    const __half2 z2 = __float2half2_rn(0.f);
    __half2* h = (__half2*)&v;
#pragma unroll
    for (int i = 0; i < 4; i++) h[i] = __hmax2(h[i], z2);

    ((uint4*)cat)[t] = v;
}

// ---------------------------------------------------------------------------
// Launch (#6 = L3 GEMM for ncu -s 5 -c 1)
// ---------------------------------------------------------------------------
extern "C" void kernel_launch(void* const* d_in, const int* in_sizes, int n_in,
                              void* d_out, int out_size)
{
    const float* h   = (const float*)d_in[0];
    const void*  sp  = d_in[1];
    const float* ws1 = (const float*)d_in[2];
    const float* bs1 = (const float*)d_in[3];
    const float* ws2 = (const float*)d_in[4];
    const float* bs2 = (const float*)d_in[5];
    const float* we1 = (const float*)d_in[6];
    const float* be1 = (const float*)d_in[7];
    const float* we2 = (const float*)d_in[8];
    const float* be2 = (const float*)d_in[9];
    const float* wo1 = (const float*)d_in[10];
    const float* bo1 = (const float*)d_in[11];
    const float* wo2 = (const float*)d_in[12];
    const float* bo2 = (const float*)d_in[13];
    float* out = (float*)d_out;

    __half *wh, *h16, *hid, *cat, *se;
    cudaGetSymbolAddress((void**)&wh,  g_wh);
    cudaGetSymbolAddress((void**)&h16, g_h16);
    cudaGetSymbolAddress((void**)&hid, g_hid);
    cudaGetSymbolAddress((void**)&cat, g_cat);
    cudaGetSymbolAddress((void**)&se,  g_se16);

    const int SM256 = 3 * (128 * SKB + 256 * SKB);   // 165888
    const int SM128 = 3 * (128 * SKB + 128 * SKB);   // 110592
    cudaFuncSetAttribute((const void*)gemm16_kernel<256, 512>,
                         cudaFuncAttributeMaxDynamicSharedMemorySize, SM256);
    cudaFuncSetAttribute((const void*)gemm16_kernel<128, 256>,
                         cudaFuncAttributeMaxDynamicSharedMemorySize, SM128);

    // #1
    detect_idx_kernel<<<1, 256>>>((const unsigned int*)sp, NTOK);

    // #2
    prep_kernel<<<PREP_BLOCKS, 256>>>(h, ws1, we1, ws2, we2, wo1, wo2, h16, wh);

    // #3: L1 fused start|end layer1: hid[2048,6144] = h @ [ws1;we1]^T, relu
    gemm16_kernel<256, 512><<<dim3(6144/256, BLROWS/128, 1), 512, SM256>>>(
        h16, wh + OFF_W1A, bs1, be1, FFD, nullptr, hid,
        6144, Dsz, Dsz, 6144, 1, 0, 0, 0, 0);

    // #4: L2 batched (z=0: start, z=1: end) -> se fp16
    gemm16_kernel<128, 256><<<dim3(Dsz/128, BLROWS/128, 2), 256, SM128>>>(
        hid, wh + OFF_W2A, bs2, be2, Dsz, nullptr, se,
        Dsz, FFD, 6144, CATD, 2, FFD, (int)(OFF_W2B - OFF_W2A), Dsz, 1);

    // #5: gather + relu -> fp16 cat
    int gthreads = NTOK * (CATD / 8);
    gather_cat_kernel<<<(gthreads + 255) / 256, 256>>>(se, sp, cat);

    // #6: L3 (dominant): hid[24576,3072] = cat @ wo1^T, relu
    gemm16_kernel<256, 512><<<dim3(FFD/256, NTOK/128, 1), 512, SM256>>>(
        cat, wh + OFF_W3, bo1, bo1, FFD, nullptr, hid,
        FFD, CATD, CATD, FFD, 1, 0, 0, 0, 0);

    // #7: L4: out[24576,768] = hid @ wo2^T (fp32)
    gemm16_kernel<256, 512><<<dim3(Dsz/256, NTOK/128, 1), 512, SM256>>>(
        hid, wh + OFF_W4, bo2, bo2, Dsz, out, nullptr,
        Dsz, FFD, FFD, Dsz, 0, 0, 0, 0, 0);
}

// round 14
// speedup vs baseline: 3.3857x; 1.8354x over previous
#include <cuda_runtime.h>
#include <cuda_fp16.h>
#include <cstdint>
#include <cstddef>

// Problem constants
#define Bsz 4
#define Lsz 512
#define Dsz 768
#define Wsz 12
#define Ksz (Lsz * Wsz)
#define NTOK (Bsz * Ksz)     // 24576
#define BLROWS (Bsz * Lsz)   // 2048
#define FFD 3072
#define CATD 1536
#define QOFF 6291456u        // 2048*3072, z-stride of Q

// fp16 weight buffer offsets (elements)
#define OFF_W1A 0u
#define OFF_W1B 2359296u
#define OFF_W2A 4718592u
#define OFF_W2B 7077888u
#define OFF_W3A 9437184u     // wo1 columns 0:768   -> [3072, 768]
#define OFF_W3B 11796480u    // wo1 columns 768:1536 -> [3072, 768]
#define OFF_W4  14155776u
#define WTOT    16515072u

// Static device scratch (allocation-free rule)
__device__ alignas(128) __half g_wh[WTOT];
__device__ alignas(128) __half g_h16[(size_t)BLROWS * Dsz];
__device__ alignas(128) __half g_hid[(size_t)NTOK * FFD];    // L1 out, later hidden
__device__ alignas(128) __half g_se16[(size_t)BLROWS * CATD]; // relu'd se
__device__ alignas(128) float  g_q[(size_t)2 * BLROWS * FFD]; // Q1|Q2, fp32
__device__ float g_zero[FFD];                                 // zero bias
__device__ int g_is64;

// ---------------------------------------------------------------------------
// span_idx dtype detection (int64 vs int32)
// ---------------------------------------------------------------------------
__global__ void detect_idx_kernel(const unsigned int* __restrict__ sp, int nhalf) {
    __shared__ int s_any;
    if (threadIdx.x == 0) s_any = 0;
    __syncthreads();
    int found = 0;
    for (int i = threadIdx.x; i < nhalf; i += blockDim.x)
        if (sp[2 * i + 1] != 0u) found = 1;
    if (found) atomicOr(&s_any, 1);
    __syncthreads();
    if (threadIdx.x == 0) g_is64 = (s_any == 0) ? 1 : 0;
}

// ---------------------------------------------------------------------------
// Fused prep: h + all weights fp32 -> fp16. wo1 is split into contiguous
// column blocks W3A (cols 0:768) and W3B (cols 768:1536).
// ---------------------------------------------------------------------------
#define QC0 393216u    // h
#define QC1 983040u    // ws1
#define QC2 1572864u   // we1
#define QC3 2162688u   // ws2
#define QC4 2752512u   // we2
#define QC5 3932160u   // wo1
#define QC6 4521984u   // wo2
#define PREP_BLOCKS ((QC6 + 255u) / 256u)

__global__ void prep_kernel(const float* __restrict__ h,
                            const float* __restrict__ ws1, const float* __restrict__ we1,
                            const float* __restrict__ ws2, const float* __restrict__ we2,
                            const float* __restrict__ wo1, const float* __restrict__ wo2,
                            __half* __restrict__ h16, __half* __restrict__ wh)
{
    unsigned int t = blockIdx.x * 256u + threadIdx.x;
    if (t >= QC6) return;
    const float* src;
    __half* dst;
    unsigned int soff, doff;
    if (t < QC0)      { src = h;   dst = h16;          soff = t;       doff = soff; }
    else if (t < QC1) { src = ws1; dst = wh + OFF_W1A; soff = t - QC0; doff = soff; }
    else if (t < QC2) { src = we1; dst = wh + OFF_W1B; soff = t - QC1; doff = soff; }
    else if (t < QC3) { src = ws2; dst = wh + OFF_W2A; soff = t - QC2; doff = soff; }
    else if (t < QC4) { src = we2; dst = wh + OFF_W2B; soff = t - QC3; doff = soff; }
    else if (t < QC5) {
        // wo1 [3072, 1536]: 384 quads/row; qcol<192 -> W3A else W3B
        src = wo1; soff = t - QC4;
        unsigned qrow = soff / 384u, qcol = soff - qrow * 384u;
        if (qcol < 192u) { dst = wh + OFF_W3A; doff = qrow * 192u + qcol; }
        else             { dst = wh + OFF_W3B; doff = qrow * 192u + qcol - 192u; }
    }
    else              { src = wo2; dst = wh + OFF_W4;  soff = t - QC5; doff = soff; }
    float4 v = ((const float4*)src)[soff];
    __half hh[4] = {__float2half_rn(v.x), __float2half_rn(v.y),
                    __float2half_rn(v.z), __float2half_rn(v.w)};
    ((uint2*)dst)[doff] = *(uint2*)hh;
}

// ---------------------------------------------------------------------------
// PTX helpers
// ---------------------------------------------------------------------------
__device__ __forceinline__ uint32_t smem_u32(const void* p) {
    return (uint32_t)__cvta_generic_to_shared(p);
}
__device__ __forceinline__ void ldm_x4(uint32_t* r, uint32_t addr) {
    asm volatile("ldmatrix.sync.aligned.m8n8.x4.shared.b16 {%0,%1,%2,%3}, [%4];"
                 : "=r"(r[0]), "=r"(r[1]), "=r"(r[2]), "=r"(r[3]) : "r"(addr));
}
__device__ __forceinline__ void mma_f16(float* d, const uint32_t* a, const uint32_t* b) {
    asm volatile(
        "mma.sync.aligned.m16n8k16.row.col.f32.f16.f16.f32 "
        "{%0,%1,%2,%3},{%4,%5,%6,%7},{%8,%9},{%0,%1,%2,%3};"
        : "+f"(d[0]), "+f"(d[1]), "+f"(d[2]), "+f"(d[3])
        : "r"(a[0]), "r"(a[1]), "r"(a[2]), "r"(a[3]), "r"(b[0]), "r"(b[1]));
}
__device__ __forceinline__ void cp16(uint32_t dst, const void* src) {
    asm volatile("cp.async.cg.shared.global [%0], [%1], 16;" :: "r"(dst), "l"(src));
}

// ---------------------------------------------------------------------------
// fp16 tensor GEMM (NT): C = A*B^T + bias, fp32 accumulate. BK=64.
// BN=256/NTHR=512: warp tile 32x64 (4x4), 16 warps, 1 CTA/SM.
// BN=128/NTHR=256: warp tile 64x32 (2x4), 2 CTAs/SM.
// 3-stage cp.async + cross-kk fragment double buffer.
// mode 0: fp32 C. mode 1: relu + fp16 C. mode 2: fp16 C (no relu).
// ---------------------------------------------------------------------------
#define SKB 144

template<int BN, int NTHR>
__global__ __launch_bounds__(NTHR, (BN == 128) ? 2 : 1)
void gemm16_kernel(const __half* __restrict__ A,
                   const __half* __restrict__ B,
                   const float* __restrict__ bias1,
                   const float* __restrict__ bias2, int nsplit,
                   float* __restrict__ Cf,
                   __half* __restrict__ Ch,
                   int N, int K, int lda, int ldc, int mode,
                   int zAoff, int zBoff, int zCoff, int zBias)
{
    constexpr int NWARP = NTHR / 32;
    constexpr int WM    = 128 / (NWARP / 4);
    constexpr int WN    = BN / 4;
    constexpr int MI    = WM / 16;
    constexpr int NP    = WN / 16;
    constexpr int NF    = WN / 8;
    constexpr int TILEA = 128 * SKB;
    constexpr int TILEB = BN * SKB;
    constexpr int STAGE = TILEA + TILEB;

    extern __shared__ char smem[];
    const uint32_t sbase = smem_u32(smem);

    const int tid  = threadIdx.x;
    const int lane = tid & 31;
    const int wid  = tid >> 5;
    const int wm   = (wid >> 2) * WM;
    const int wn   = (wid & 3) * WN;
    const int bm   = blockIdx.y << 7;
    const int bn   = blockIdx.x * BN;
    const int z    = blockIdx.z;

    const __half* aSrc = A + (size_t)z * zAoff + (size_t)bm * lda;
    const __half* bSrc = B + (size_t)z * zBoff + (size_t)bn * K;

    float acc[MI][NF][4];
#pragma unroll
    for (int i = 0; i < MI; i++)
#pragma unroll
        for (int j = 0; j < NF; j++)
#pragma unroll
            for (int r = 0; r < 4; r++) acc[i][j][r] = 0.f;

    const int nk = K >> 6;

    auto issue = [&](int kt) {
        const uint32_t st = sbase + (kt % 3) * STAGE;
        const int kb = kt << 6;
#pragma unroll
        for (int c = tid; c < 1024; c += NTHR) {
            const int row = c >> 3, ch = c & 7;
            cp16(st + (uint32_t)row * SKB + ch * 16,
                 aSrc + (size_t)row * lda + kb + ch * 8);
        }
#pragma unroll
        for (int c = tid; c < BN * 8; c += NTHR) {
            const int row = c >> 3, ch = c & 7;
            cp16(st + TILEA + (uint32_t)row * SKB + ch * 16,
                 bSrc + (size_t)row * K + kb + ch * 8);
        }
    };

    const int aq    = lane >> 3;
    const int arow  = ((aq & 1) << 3) + (lane & 7);
    const int acol  = (aq >> 1) << 3;
    const int brow4 = ((lane >> 4) << 3) + (lane & 7);
    const int bcol4 = ((lane >> 3) & 1) << 3;

    uint32_t a[2][MI][4], bb[2][NP][4];

    auto ldfrag = [&](uint32_t st, int kk, int fb) {
#pragma unroll
        for (int mi = 0; mi < MI; mi++) {
            const uint32_t off = (uint32_t)(wm + mi * 16 + arow) * SKB + (kk + acol) * 2;
            ldm_x4(a[fb][mi], st + off);
        }
#pragma unroll
        for (int p = 0; p < NP; p++) {
            const uint32_t off = (uint32_t)(wn + p * 16 + brow4) * SKB + (kk + bcol4) * 2;
            ldm_x4(bb[fb][p], st + TILEA + off);
        }
    };

    issue(0);
    asm volatile("cp.async.commit_group;" ::: "memory");
    issue(1);
    asm volatile("cp.async.commit_group;" ::: "memory");

    for (int kt = 0; kt < nk; kt++) {
        asm volatile("cp.async.wait_group 1;" ::: "memory");
        __syncthreads();
        if (kt + 2 < nk) issue(kt + 2);
        asm volatile("cp.async.commit_group;" ::: "memory");

        const uint32_t st = sbase + (kt % 3) * STAGE;

        ldfrag(st, 0, 0);
#pragma unroll
        for (int j = 0; j < 4; j++) {
            const int cur = j & 1;
            if (j < 3) ldfrag(st, (j + 1) * 16, cur ^ 1);
#pragma unroll
            for (int mi = 0; mi < MI; mi++)
#pragma unroll
                for (int p = 0; p < NP; p++) {
                    mma_f16(acc[mi][2 * p],     a[cur][mi], &bb[cur][p][0]);
                    mma_f16(acc[mi][2 * p + 1], a[cur][mi], &bb[cur][p][2]);
                }
        }
    }

    // Epilogue
    float* Cfz = Cf ? Cf + (size_t)z * zCoff : nullptr;
    __half* Chz = Ch ? Ch + (size_t)z * zCoff : nullptr;
    const float* bA = (zBias && z) ? bias2 : bias1;

    const int lr = lane >> 2;
    const int lc = (lane & 3) * 2;
#pragma unroll
    for (int mi = 0; mi < MI; mi++) {
#pragma unroll
        for (int ni = 0; ni < NF; ni++) {
            const int gm = bm + wm + mi * 16 + lr;
            const int gc = bn + wn + ni * 8 + lc;
            const float b0 = (gc < nsplit)     ? bA[gc]     : bias2[gc - nsplit];
            const float b1 = (gc + 1 < nsplit) ? bA[gc + 1] : bias2[gc + 1 - nsplit];
            float v0 = acc[mi][ni][0] + b0;
            float v1 = acc[mi][ni][1] + b1;
            float v2 = acc[mi][ni][2] + b0;
            float v3 = acc[mi][ni][3] + b1;
            if (mode == 0) {
                *(float2*)(Cfz + (size_t)gm * ldc + gc)       = make_float2(v0, v1);
                *(float2*)(Cfz + (size_t)(gm + 8) * ldc + gc) = make_float2(v2, v3);
            } else {
                if (mode == 1) {
                    v0 = fmaxf(v0, 0.f); v1 = fmaxf(v1, 0.f);
                    v2 = fmaxf(v2, 0.f); v3 = fmaxf(v3, 0.f);
                }
                __half p01[2] = {__float2half_rn(v0), __float2half_rn(v1)};
                __half p23[2] = {__float2half_rn(v2), __float2half_rn(v3)};
                *(uint32_t*)(Chz + (size_t)gm * ldc + gc)       = *(uint32_t*)p01;
                *(uint32_t*)(Chz + (size_t)(gm + 8) * ldc + gc) = *(uint32_t*)p23;
            }
        }
    }
}

// ---------------------------------------------------------------------------
// Combine: hidden[r] = relu(Q1[b, s_r] + Q2[b, e_r] + bo1), fp16 out.
// One thread per 8-element chunk of the 24576 x 3072 hidden matrix.
// ---------------------------------------------------------------------------
__global__ void combine_kernel(const float* __restrict__ q,
                               const void* __restrict__ span,
                               const float* __restrict__ bo1,
                               __half* __restrict__ hidden)
{
    const int QD = FFD / 8;   // 384 chunks per row
    int t = blockIdx.x * blockDim.x + threadIdx.x;
    if (t >= NTOK * QD) return;
    int r = t / QD;
    int c = (t - r * QD) * 8;
    int b = r / Ksz;

    long long s, e;
    if (g_is64) {
        const long long* sp = (const long long*)span;
        s = sp[2 * (size_t)r]; e = sp[2 * (size_t)r + 1];
    } else {
        const int* sp = (const int*)span;
        s = sp[2 * (size_t)r]; e = sp[2 * (size_t)r + 1];
    }

    const float* p1 = q + ((size_t)(b * Lsz) + s) * FFD + c;
    const float* p2 = q + QOFF + ((size_t)(b * Lsz) + e) * FFD + c;

    __half out[8];
#pragma unroll
    for (int i = 0; i < 8; i += 4) {
        float4 x = *(const float4*)(p1 + i);
        float4 y = *(const float4*)(p2 + i);
        float4 bi = *(const float4*)(bo1 + c + i);
        out[i + 0] = __float2half_rn(fmaxf(x.x + y.x + bi.x, 0.f));
        out[i + 1] = __float2half_rn(fmaxf(x.y + y.y + bi.y, 0.f));
        out[i + 2] = __float2half_rn(fmaxf(x.z + y.z + bi.z, 0.f));
        out[i + 3] = __float2half_rn(fmaxf(x.w + y.w + bi.w, 0.f));
    }
    ((uint4*)hidden)[t] = *(uint4*)out;
}

// ---------------------------------------------------------------------------
// Launch
// ---------------------------------------------------------------------------
extern "C" void kernel_launch(void* const* d_in, const int* in_sizes, int n_in,
                              void* d_out, int out_size)
{
    const float* h   = (const float*)d_in[0];
    const void*  sp  = d_in[1];
    const float* ws1 = (const float*)d_in[2];
    const float* bs1 = (const float*)d_in[3];
    const float* ws2 = (const float*)d_in[4];
    const float* bs2 = (const float*)d_in[5];
    const float* we1 = (const float*)d_in[6];
    const float* be1 = (const float*)d_in[7];
    const float* we2 = (const float*)d_in[8];
    const float* be2 = (const float*)d_in[9];
    const float* wo1 = (const float*)d_in[10];
    const float* bo1 = (const float*)d_in[11];
    const float* wo2 = (const float*)d_in[12];
    const float* bo2 = (const float*)d_in[13];
    float* out = (float*)d_out;

    __half *wh, *h16, *hid, *se;
    float *qbuf, *zeros;
    cudaGetSymbolAddress((void**)&wh,    g_wh);
    cudaGetSymbolAddress((void**)&h16,   g_h16);
    cudaGetSymbolAddress((void**)&hid,   g_hid);
    cudaGetSymbolAddress((void**)&se,    g_se16);
    cudaGetSymbolAddress((void**)&qbuf,  g_q);
    cudaGetSymbolAddress((void**)&zeros, g_zero);

    const int SM256 = 3 * (128 * SKB + 256 * SKB);   // 165888
    const int SM128 = 3 * (128 * SKB + 128 * SKB);   // 110592
    cudaFuncSetAttribute((const void*)gemm16_kernel<256, 512>,
                         cudaFuncAttributeMaxDynamicSharedMemorySize, SM256);
    cudaFuncSetAttribute((const void*)gemm16_kernel<128, 256>,
                         cudaFuncAttributeMaxDynamicSharedMemorySize, SM128);

    // #1: span dtype detect
    detect_idx_kernel<<<1, 256>>>((const unsigned int*)sp, NTOK);

    // #2: fp32->fp16 conversions (wo1 split into W3A|W3B)
    prep_kernel<<<PREP_BLOCKS, 256>>>(h, ws1, we1, ws2, we2, wo1, wo2, h16, wh);

    // #3: L1 fused start|end layer1: hid[2048,6144] = h @ [ws1;we1]^T, relu
    gemm16_kernel<256, 512><<<dim3(6144/256, BLROWS/128, 1), 512, SM256>>>(
        h16, wh + OFF_W1A, bs1, be1, FFD, nullptr, hid,
        6144, Dsz, Dsz, 6144, 1, 0, 0, 0, 0);

    // #4: L2 batched (z=0 start, z=1 end) -> se_relu fp16 [2048, 1536]
    gemm16_kernel<128, 256><<<dim3(Dsz/128, BLROWS/128, 2), 256, SM128>>>(
        hid, wh + OFF_W2A, bs2, be2, Dsz, nullptr, se,
        Dsz, FFD, 6144, CATD, 1, FFD, (int)(OFF_W2B - OFF_W2A), Dsz, 1);

    // #5: Q batched (z=0: se[:, :768]@W3A^T; z=1: se[:, 768:]@W3B^T), fp32 out
    gemm16_kernel<256, 512><<<dim3(FFD/256, BLROWS/128, 2), 512, SM256>>>(
        se, wh + OFF_W3A, zeros, zeros, FFD, qbuf, nullptr,
        FFD, Dsz, CATD, FFD, 0, Dsz, (int)(OFF_W3B - OFF_W3A), (int)QOFF, 1);

    // #6: combine: hidden[24576,3072] = relu(Q1[s] + Q2[e] + bo1), fp16
    {
        int nthr = NTOK * (FFD / 8);
        combine_kernel<<<(nthr + 255) / 256, 256>>>(qbuf, sp, bo1, hid);
    }

    // #7: L4: out[24576,768] = hidden @ wo2^T + bo2 (fp32)
    gemm16_kernel<256, 512><<<dim3(Dsz/256, NTOK/128, 1), 512, SM256>>>(
        hid, wh + OFF_W4, bo2, bo2, Dsz, out, nullptr,
        Dsz, FFD, FFD, Dsz, 0, 0, 0, 0, 0);
}

// round 15
// speedup vs baseline: 3.6612x; 1.0814x over previous
#include <cuda_runtime.h>
#include <cuda_fp16.h>
#include <cstdint>
#include <cstddef>

// Problem constants
#define Bsz 4
#define Lsz 512
#define Dsz 768
#define Wsz 12
#define Ksz (Lsz * Wsz)
#define NTOK (Bsz * Ksz)     // 24576
#define BLROWS (Bsz * Lsz)   // 2048
#define FFD 3072
#define CATD 1536
#define QOFF 6291456u        // 2048*3072, z-stride of Q

// fp16 weight buffer offsets (elements)
#define OFF_W1A 0u
#define OFF_W1B 2359296u
#define OFF_W2A 4718592u
#define OFF_W2B 7077888u
#define OFF_W3A 9437184u     // wo1 cols 0:768   -> [3072, 768]
#define OFF_W3B 11796480u    // wo1 cols 768:1536 -> [3072, 768]
#define OFF_W4  14155776u
#define WTOT    16515072u

// Static device scratch (allocation-free rule)
__device__ alignas(128) __half g_wh[WTOT];
__device__ alignas(128) __half g_h16[(size_t)BLROWS * Dsz];
__device__ alignas(128) __half g_hid[(size_t)NTOK * FFD];     // L1 out, later hidden
__device__ alignas(128) __half g_se16[(size_t)BLROWS * CATD]; // relu'd se
__device__ alignas(128) float  g_q[(size_t)2 * BLROWS * FFD]; // Q1|Q2, fp32
__device__ float g_zero[FFD];
__device__ int g_is64;

// ---------------------------------------------------------------------------
// Fused prep: h + all weights fp32 -> fp16, wo1 split into W3A|W3B.
// Extra last block performs span_idx dtype detection.
// ---------------------------------------------------------------------------
#define QC0 393216u    // h
#define QC1 983040u    // ws1
#define QC2 1572864u   // we1
#define QC3 2162688u   // ws2
#define QC4 2752512u   // we2
#define QC5 3932160u   // wo1
#define QC6 4521984u   // wo2
#define PREP_BLOCKS ((QC6 + 255u) / 256u)

__global__ void prep_kernel(const float* __restrict__ h,
                            const float* __restrict__ ws1, const float* __restrict__ we1,
                            const float* __restrict__ ws2, const float* __restrict__ we2,
                            const float* __restrict__ wo1, const float* __restrict__ wo2,
                            __half* __restrict__ h16, __half* __restrict__ wh,
                            const unsigned int* __restrict__ sp)
{
    if (blockIdx.x == PREP_BLOCKS) {
        // span dtype detection: int64 high-halves all zero <=> is64
        __shared__ int s_any;
        if (threadIdx.x == 0) s_any = 0;
        __syncthreads();
        int found = 0;
        for (int i = threadIdx.x; i < NTOK; i += blockDim.x)
            if (sp[2 * i + 1] != 0u) found = 1;
        if (found) atomicOr(&s_any, 1);
        __syncthreads();
        if (threadIdx.x == 0) g_is64 = (s_any == 0) ? 1 : 0;
        return;
    }

    unsigned int t = blockIdx.x * 256u + threadIdx.x;
    if (t >= QC6) return;
    const float* src;
    __half* dst;
    unsigned int soff, doff;
    if (t < QC0)      { src = h;   dst = h16;          soff = t;       doff = soff; }
    else if (t < QC1) { src = ws1; dst = wh + OFF_W1A; soff = t - QC0; doff = soff; }
    else if (t < QC2) { src = we1; dst = wh + OFF_W1B; soff = t - QC1; doff = soff; }
    else if (t < QC3) { src = ws2; dst = wh + OFF_W2A; soff = t - QC2; doff = soff; }
    else if (t < QC4) { src = we2; dst = wh + OFF_W2B; soff = t - QC3; doff = soff; }
    else if (t < QC5) {
        src = wo1; soff = t - QC4;
        unsigned qrow = soff / 384u, qcol = soff - qrow * 384u;
        if (qcol < 192u) { dst = wh + OFF_W3A; doff = qrow * 192u + qcol; }
        else             { dst = wh + OFF_W3B; doff = qrow * 192u + qcol - 192u; }
    }
    else              { src = wo2; dst = wh + OFF_W4;  soff = t - QC5; doff = soff; }
    float4 v = ((const float4*)src)[soff];
    __half hh[4] = {__float2half_rn(v.x), __float2half_rn(v.y),
                    __float2half_rn(v.z), __float2half_rn(v.w)};
    ((uint2*)dst)[doff] = *(uint2*)hh;
}

// ---------------------------------------------------------------------------
// PTX helpers
// ---------------------------------------------------------------------------
__device__ __forceinline__ uint32_t smem_u32(const void* p) {
    return (uint32_t)__cvta_generic_to_shared(p);
}
__device__ __forceinline__ void ldm_x4(uint32_t* r, uint32_t addr) {
    asm volatile("ldmatrix.sync.aligned.m8n8.x4.shared.b16 {%0,%1,%2,%3}, [%4];"
                 : "=r"(r[0]), "=r"(r[1]), "=r"(r[2]), "=r"(r[3]) : "r"(addr));
}
__device__ __forceinline__ void mma_f16(float* d, const uint32_t* a, const uint32_t* b) {
    asm volatile(
        "mma.sync.aligned.m16n8k16.row.col.f32.f16.f16.f32 "
        "{%0,%1,%2,%3},{%4,%5,%6,%7},{%8,%9},{%0,%1,%2,%3};"
        : "+f"(d[0]), "+f"(d[1]), "+f"(d[2]), "+f"(d[3])
        : "r"(a[0]), "r"(a[1]), "r"(a[2]), "r"(a[3]), "r"(b[0]), "r"(b[1]));
}
__device__ __forceinline__ void cp16(uint32_t dst, const void* src) {
    asm volatile("cp.async.cg.shared.global [%0], [%1], 16;" :: "r"(dst), "l"(src));
}

// ---------------------------------------------------------------------------
// fp16 tensor GEMM (NT): C = A*B^T + bias, fp32 accumulate. BK=64.
// BN=256/NTHR=256: warp tile 64x64 (2x4 warps), 1 CTA/SM — low smem B/MAC
//                  (LDSM 128KB + writes 48KB per K-tile vs tensor 1824cyc).
// BN=128/NTHR=256: warp tile 64x32 (2x4), 2 CTAs/SM (small-N layers).
// 3-stage cp.async + cross-kk fragment double buffer.
// mode 0: fp32 C. mode 1: relu + fp16 C. mode 2: fp16 C (no relu).
// ---------------------------------------------------------------------------
#define SKB 144

template<int BN, int NTHR>
__global__ __launch_bounds__(NTHR, (BN == 128) ? 2 : 1)
void gemm16_kernel(const __half* __restrict__ A,
                   const __half* __restrict__ B,
                   const float* __restrict__ bias1,
                   const float* __restrict__ bias2, int nsplit,
                   float* __restrict__ Cf,
                   __half* __restrict__ Ch,
                   int N, int K, int lda, int ldc, int mode,
                   int zAoff, int zBoff, int zCoff, int zBias)
{
    constexpr int NWARP = NTHR / 32;
    constexpr int WM    = 128 / (NWARP / 4);   // 64 (8 warps)
    constexpr int WN    = BN / 4;              // 64 or 32
    constexpr int MI    = WM / 16;             // 4
    constexpr int NP    = WN / 16;             // 4 or 2
    constexpr int NF    = WN / 8;              // 8 or 4
    constexpr int TILEA = 128 * SKB;
    constexpr int TILEB = BN * SKB;
    constexpr int STAGE = TILEA + TILEB;

    extern __shared__ char smem[];
    const uint32_t sbase = smem_u32(smem);

    const int tid  = threadIdx.x;
    const int lane = tid & 31;
    const int wid  = tid >> 5;
    const int wm   = (wid >> 2) * WM;
    const int wn   = (wid & 3) * WN;
    const int bm   = blockIdx.y << 7;
    const int bn   = blockIdx.x * BN;
    const int z    = blockIdx.z;

    const __half* aSrc = A + (size_t)z * zAoff + (size_t)bm * lda;
    const __half* bSrc = B + (size_t)z * zBoff + (size_t)bn * K;

    float acc[MI][NF][4];
#pragma unroll
    for (int i = 0; i < MI; i++)
#pragma unroll
        for (int j = 0; j < NF; j++)
#pragma unroll
            for (int r = 0; r < 4; r++) acc[i][j][r] = 0.f;

    const int nk = K >> 6;

    auto issue = [&](int kt) {
        const uint32_t st = sbase + (kt % 3) * STAGE;
        const int kb = kt << 6;
#pragma unroll
        for (int c = tid; c < 1024; c += NTHR) {
            const int row = c >> 3, ch = c & 7;
            cp16(st + (uint32_t)row * SKB + ch * 16,
                 aSrc + (size_t)row * lda + kb + ch * 8);
        }
#pragma unroll
        for (int c = tid; c < BN * 8; c += NTHR) {
            const int row = c >> 3, ch = c & 7;
            cp16(st + TILEA + (uint32_t)row * SKB + ch * 16,
                 bSrc + (size_t)row * K + kb + ch * 8);
        }
    };

    const int aq    = lane >> 3;
    const int arow  = ((aq & 1) << 3) + (lane & 7);
    const int acol  = (aq >> 1) << 3;
    const int brow4 = ((lane >> 4) << 3) + (lane & 7);
    const int bcol4 = ((lane >> 3) & 1) << 3;

    uint32_t a[2][MI][4], bb[2][NP][4];

    auto ldfrag = [&](uint32_t st, int kk, int fb) {
#pragma unroll
        for (int mi = 0; mi < MI; mi++) {
            const uint32_t off = (uint32_t)(wm + mi * 16 + arow) * SKB + (kk + acol) * 2;
            ldm_x4(a[fb][mi], st + off);
        }
#pragma unroll
        for (int p = 0; p < NP; p++) {
            const uint32_t off = (uint32_t)(wn + p * 16 + brow4) * SKB + (kk + bcol4) * 2;
            ldm_x4(bb[fb][p], st + TILEA + off);
        }
    };

    issue(0);
    asm volatile("cp.async.commit_group;" ::: "memory");
    issue(1);
    asm volatile("cp.async.commit_group;" ::: "memory");

    for (int kt = 0; kt < nk; kt++) {
        asm volatile("cp.async.wait_group 1;" ::: "memory");
        __syncthreads();
        if (kt + 2 < nk) issue(kt + 2);
        asm volatile("cp.async.commit_group;" ::: "memory");

        const uint32_t st = sbase + (kt % 3) * STAGE;

        ldfrag(st, 0, 0);
#pragma unroll
        for (int j = 0; j < 4; j++) {
            const int cur = j & 1;
            if (j < 3) ldfrag(st, (j + 1) * 16, cur ^ 1);
#pragma unroll
            for (int mi = 0; mi < MI; mi++)
#pragma unroll
                for (int p = 0; p < NP; p++) {
                    mma_f16(acc[mi][2 * p],     a[cur][mi], &bb[cur][p][0]);
                    mma_f16(acc[mi][2 * p + 1], a[cur][mi], &bb[cur][p][2]);
                }
        }
    }

    // Epilogue
    float* Cfz = Cf ? Cf + (size_t)z * zCoff : nullptr;
    __half* Chz = Ch ? Ch + (size_t)z * zCoff : nullptr;
    const float* bA = (zBias && z) ? bias2 : bias1;

    const int lr = lane >> 2;
    const int lc = (lane & 3) * 2;
#pragma unroll
    for (int mi = 0; mi < MI; mi++) {
#pragma unroll
        for (int ni = 0; ni < NF; ni++) {
            const int gm = bm + wm + mi * 16 + lr;
            const int gc = bn + wn + ni * 8 + lc;
            const float b0 = (gc < nsplit)     ? bA[gc]     : bias2[gc - nsplit];
            const float b1 = (gc + 1 < nsplit) ? bA[gc + 1] : bias2[gc + 1 - nsplit];
            float v0 = acc[mi][ni][0] + b0;
            float v1 = acc[mi][ni][1] + b1;
            float v2 = acc[mi][ni][2] + b0;
            float v3 = acc[mi][ni][3] + b1;
            if (mode == 0) {
                *(float2*)(Cfz + (size_t)gm * ldc + gc)       = make_float2(v0, v1);
                *(float2*)(Cfz + (size_t)(gm + 8) * ldc + gc) = make_float2(v2, v3);
            } else {
                if (mode == 1) {
                    v0 = fmaxf(v0, 0.f); v1 = fmaxf(v1, 0.f);
                    v2 = fmaxf(v2, 0.f); v3 = fmaxf(v3, 0.f);
                }
                __half p01[2] = {__float2half_rn(v0), __float2half_rn(v1)};
                __half p23[2] = {__float2half_rn(v2), __float2half_rn(v3)};
                *(uint32_t*)(Chz + (size_t)gm * ldc + gc)       = *(uint32_t*)p01;
                *(uint32_t*)(Chz + (size_t)(gm + 8) * ldc + gc) = *(uint32_t*)p23;
            }
        }
    }
}

// ---------------------------------------------------------------------------
// Combine: hidden[r] = relu(Q1[b, s_r] + Q2[b, e_r] + bo1), fp16 out.
// ---------------------------------------------------------------------------
__global__ void combine_kernel(const float* __restrict__ q,
                               const void* __restrict__ span,
                               const float* __restrict__ bo1,
                               __half* __restrict__ hidden)
{
    const int QD = FFD / 8;
    int t = blockIdx.x * blockDim.x + threadIdx.x;
    if (t >= NTOK * QD) return;
    int r = t / QD;
    int c = (t - r * QD) * 8;
    int b = r / Ksz;

    long long s, e;
    if (g_is64) {
        const long long* sp = (const long long*)span;
        s = sp[2 * (size_t)r]; e = sp[2 * (size_t)r + 1];
    } else {
        const int* sp = (const int*)span;
        s = sp[2 * (size_t)r]; e = sp[2 * (size_t)r + 1];
    }

    const float* p1 = q + ((size_t)(b * Lsz) + s) * FFD + c;
    const float* p2 = q + QOFF + ((size_t)(b * Lsz) + e) * FFD + c;

    __half out[8];
#pragma unroll
    for (int i = 0; i < 8; i += 4) {
        float4 x = *(const float4*)(p1 + i);
        float4 y = *(const float4*)(p2 + i);
        float4 bi = *(const float4*)(bo1 + c + i);
        out[i + 0] = __float2half_rn(fmaxf(x.x + y.x + bi.x, 0.f));
        out[i + 1] = __float2half_rn(fmaxf(x.y + y.y + bi.y, 0.f));
        out[i + 2] = __float2half_rn(fmaxf(x.z + y.z + bi.z, 0.f));
        out[i + 3] = __float2half_rn(fmaxf(x.w + y.w + bi.w, 0.f));
    }
    ((uint4*)hidden)[t] = *(uint4*)out;
}

// ---------------------------------------------------------------------------
// Launch. Order: prep(1), L1(2), L2(3), Q(4), combine(5), L4(6) — ncu -s 5
// captures L4, the dominant GEMM.
// ---------------------------------------------------------------------------
extern "C" void kernel_launch(void* const* d_in, const int* in_sizes, int n_in,
                              void* d_out, int out_size)
{
    const float* h   = (const float*)d_in[0];
    const void*  sp  = d_in[1];
    const float* ws1 = (const float*)d_in[2];
    const float* bs1 = (const float*)d_in[3];
    const float* ws2 = (const float*)d_in[4];
    const float* bs2 = (const float*)d_in[5];
    const float* we1 = (const float*)d_in[6];
    const float* be1 = (const float*)d_in[7];
    const float* we2 = (const float*)d_in[8];
    const float* be2 = (const float*)d_in[9];
    const float* wo1 = (const float*)d_in[10];
    const float* bo1 = (const float*)d_in[11];
    const float* wo2 = (const float*)d_in[12];
    const float* bo2 = (const float*)d_in[13];
    float* out = (float*)d_out;

    __half *wh, *h16, *hid, *se;
    float *qbuf, *zeros;
    cudaGetSymbolAddress((void**)&wh,    g_wh);
    cudaGetSymbolAddress((void**)&h16,   g_h16);
    cudaGetSymbolAddress((void**)&hid,   g_hid);
    cudaGetSymbolAddress((void**)&se,    g_se16);
    cudaGetSymbolAddress((void**)&qbuf,  g_q);
    cudaGetSymbolAddress((void**)&zeros, g_zero);

    const int SM256 = 3 * (128 * SKB + 256 * SKB);   // 165888
    const int SM128 = 3 * (128 * SKB + 128 * SKB);   // 110592
    cudaFuncSetAttribute((const void*)gemm16_kernel<256, 256>,
                         cudaFuncAttributeMaxDynamicSharedMemorySize, SM256);
    cudaFuncSetAttribute((const void*)gemm16_kernel<128, 256>,
                         cudaFuncAttributeMaxDynamicSharedMemorySize, SM128);

    // #1: prep (conversions + span dtype detect in extra block)
    prep_kernel<<<PREP_BLOCKS + 1, 256>>>(h, ws1, we1, ws2, we2, wo1, wo2,
                                          h16, wh, (const unsigned int*)sp);

    // #2: L1 fused start|end layer1: hid[2048,6144] = h @ [ws1;we1]^T, relu
    gemm16_kernel<256, 256><<<dim3(6144/256, BLROWS/128, 1), 256, SM256>>>(
        h16, wh + OFF_W1A, bs1, be1, FFD, nullptr, hid,
        6144, Dsz, Dsz, 6144, 1, 0, 0, 0, 0);

    // #3: L2 batched (z=0 start, z=1 end) -> se_relu fp16 [2048, 1536]
    gemm16_kernel<128, 256><<<dim3(Dsz/128, BLROWS/128, 2), 256, SM128>>>(
        hid, wh + OFF_W2A, bs2, be2, Dsz, nullptr, se,
        Dsz, FFD, 6144, CATD, 1, FFD, (int)(OFF_W2B - OFF_W2A), Dsz, 1);

    // #4: Q batched (z=0: se[:, :768]@W3A^T; z=1: se[:, 768:]@W3B^T), fp32 out
    gemm16_kernel<256, 256><<<dim3(FFD/256, BLROWS/128, 2), 256, SM256>>>(
        se, wh + OFF_W3A, zeros, zeros, FFD, qbuf, nullptr,
        FFD, Dsz, CATD, FFD, 0, Dsz, (int)(OFF_W3B - OFF_W3A), (int)QOFF, 1);

    // #5: combine: hidden[24576,3072] = relu(Q1[s] + Q2[e] + bo1), fp16
    {
        int nthr = NTOK * (FFD / 8);
        combine_kernel<<<(nthr + 255) / 256, 256>>>(qbuf, sp, bo1, hid);
    }

    // #6: L4 (dominant, profiled): out[24576,768] = hidden @ wo2^T + bo2 (fp32)
    gemm16_kernel<256, 256><<<dim3(Dsz/256, NTOK/128, 1), 256, SM256>>>(
        hid, wh + OFF_W4, bo2, bo2, Dsz, out, nullptr,
        Dsz, FFD, FFD, Dsz, 0, 0, 0, 0, 0);
}